// round 10
// baseline (speedup 1.0000x reference)
#include <cuda_runtime.h>
#include <stdint.h>
#include <math.h>

// Shapes (fixed): T=64, B=1, C=768, V=H*W*D=512, heads=12, hd=64, M=T*V=32768

__device__ float g_scale[64 * 768];
__device__ float g_shift[64 * 768];
__device__ float g_qa[64 * 12];
__device__ float g_invqa[64 * 12];
__device__ float g_sb[12 * 2304];
__device__ int   g_xq[64 * 192 * 512];   // x int8 packed: [t][kw][v]
__device__ int   g_wq[192 * 2304];       // w_in int8 packed: [kw][o]
__device__ float g_bias[12 * 64 * 64];
__device__ float g_q[512 * 12 * 64 * 64];
__device__ float g_k[512 * 12 * 64 * 64];
__device__ float g_v[512 * 12 * 64 * 64];
__device__ int   g_oq[32768 * 192];      // attn out int8 packed: [n][kw]
__device__ float g_sa2[32768 * 12];      // attn out scale per (n, head)
__device__ int   g_wq2[192 * 768];       // w_out int8 packed: [kw][oc]
__device__ float g_sb2[12 * 768];        // w_out scale per (chunk, oc)

__device__ __forceinline__ void cp16(void* smem, const void* g) {
    unsigned int s = (unsigned int)__cvta_generic_to_shared(smem);
    asm volatile("cp.async.cg.shared.global [%0], [%1], 16;" :: "r"(s), "l"(g));
}
__device__ __forceinline__ int q8(float f) {
    int q = __float2int_rn(f);
    q = q > 127 ? 127 : q;
    q = q < -127 ? -127 : q;
    return q & 0xFF;
}

// ---------------------------------------------------------------------------
// 1) GroupNorm stats + per-(t,chunk) quant bounds
// ---------------------------------------------------------------------------
__global__ void gn_stats_kernel(const float* __restrict__ x,
                                const float* __restrict__ w) {
    const int t = blockIdx.x / 12;
    const int g = blockIdx.x % 12;
    const int tid = threadIdx.x;
    const int cl = tid >> 2;
    const int qq = tid & 3;
    const float* base = x + (size_t)t * 393216 + (size_t)(g * 64 + cl) * 512 + qq * 128;

    float s = 0.f, s2 = 0.f, mx = 0.f;
    #pragma unroll 8
    for (int i = 0; i < 32; i++) {
        float4 a = ((const float4*)base)[i];
        s  += a.x + a.y + a.z + a.w;
        s2 += a.x * a.x + a.y * a.y + a.z * a.z + a.w * a.w;
        mx = fmaxf(mx, fmaxf(fmaxf(fabsf(a.x), fabsf(a.y)), fmaxf(fabsf(a.z), fabsf(a.w))));
    }
    __shared__ float red[256], red2[256], rmax[256];
    red[tid] = s; red2[tid] = s2; rmax[tid] = mx;
    __syncthreads();
    for (int o = 128; o > 0; o >>= 1) {
        if (tid < o) {
            red[tid]  += red[tid + o];
            red2[tid] += red2[tid + o];
        }
        __syncthreads();
    }
    __shared__ float smu, sinv;
    if (tid == 0) {
        float mu  = red[0] * (1.f / 32768.f);
        float var = red2[0] * (1.f / 32768.f) - mu * mu;
        smu  = mu;
        sinv = rsqrtf(var + 1e-5f);
    }
    __syncthreads();
    const float mu = smu, inv = sinv;
    if (tid < 64) {
        float cm = fmaxf(fmaxf(rmax[tid * 4], rmax[tid * 4 + 1]),
                         fmaxf(rmax[tid * 4 + 2], rmax[tid * 4 + 3]));
        int c = g * 64 + tid;
        float sc = inv * w[c];
        g_scale[t * 768 + c] = sc;
        g_shift[t * 768 + c] = -mu * sc;
        red[tid] = fabsf(sc) * (cm + fabsf(mu));
    }
    __syncthreads();
    for (int o = 32; o > 0; o >>= 1) {
        if (tid < o && tid + o < 64) red[tid] = fmaxf(red[tid], red[tid + o]);
        __syncthreads();
    }
    if (tid == 0) {
        float bound = red[0];
        if (bound < 1e-30f) {
            g_qa[t * 12 + g] = 0.f;
            g_invqa[t * 12 + g] = 0.f;
        } else {
            g_qa[t * 12 + g] = bound * (1.f / 127.f);
            g_invqa[t * 12 + g] = 127.f / bound;
        }
    }
}

// ---------------------------------------------------------------------------
// 1b) quantize + k-pack xn -> g_xq[t][kw][v]
// ---------------------------------------------------------------------------
__global__ void __launch_bounds__(128) quant_x_kernel(const float* __restrict__ x) {
    const int b = blockIdx.x;
    const int t = b / 192;
    const int kw = b % 192;
    const int ch = kw >> 4;
    const int tid = threadIdx.x;
    const float qinv = g_invqa[t * 12 + ch];
    const int c0 = kw * 4;

    int w[4] = {0, 0, 0, 0};
    #pragma unroll
    for (int r = 0; r < 4; r++) {
        int c = c0 + r;
        float scm = g_scale[t * 768 + c] * qinv;
        float shm = g_shift[t * 768 + c] * qinv;
        float4 f = *(const float4*)(x + (size_t)t * 393216 + (size_t)c * 512 + tid * 4);
        w[0] |= q8(fmaf(f.x, scm, shm)) << (8 * r);
        w[1] |= q8(fmaf(f.y, scm, shm)) << (8 * r);
        w[2] |= q8(fmaf(f.z, scm, shm)) << (8 * r);
        w[3] |= q8(fmaf(f.w, scm, shm)) << (8 * r);
    }
    *(int4*)(g_xq + ((size_t)t * 192 + kw) * 512 + tid * 4) = make_int4(w[0], w[1], w[2], w[3]);
}

// ---------------------------------------------------------------------------
// 1c) quantize w_in -> g_wq[kw][o], g_sb[ch][o]
// ---------------------------------------------------------------------------
__global__ void __launch_bounds__(256) quant_w_kernel(const float* __restrict__ w_in) {
    const int o = blockIdx.x * 8 + (threadIdx.x >> 5);
    const int lane = threadIdx.x & 31;
    #pragma unroll
    for (int ch = 0; ch < 12; ch++) {
        float4 wv = *(const float4*)(w_in + (size_t)o * 768 + ch * 64 + (lane & 15) * 4);
        float m = fmaxf(fmaxf(fabsf(wv.x), fabsf(wv.y)), fmaxf(fabsf(wv.z), fabsf(wv.w)));
        #pragma unroll
        for (int s = 16; s; s >>= 1) m = fmaxf(m, __shfl_xor_sync(0xffffffffu, m, s));
        float sc, invw;
        if (m < 1e-30f) { sc = 0.f; invw = 0.f; }
        else            { sc = m * (1.f / 127.f); invw = 127.f / m; }
        if (lane < 16) {
            int word = (q8(wv.x * invw))
                     | (q8(wv.y * invw) << 8)
                     | (q8(wv.z * invw) << 16)
                     | (q8(wv.w * invw) << 24);
            g_wq[(size_t)(ch * 16 + lane) * 2304 + o] = word;
        }
        if (lane == 0) g_sb[ch * 2304 + o] = sc;
    }
}

// ---------------------------------------------------------------------------
// 1d) quantize w_out -> g_wq2[kw][oc], g_sb2[ch][oc]
// ---------------------------------------------------------------------------
__global__ void __launch_bounds__(256) quant_wout_kernel(const float* __restrict__ w_out) {
    const int o = blockIdx.x * 8 + (threadIdx.x >> 5);
    const int lane = threadIdx.x & 31;
    #pragma unroll
    for (int ch = 0; ch < 12; ch++) {
        float4 wv = *(const float4*)(w_out + (size_t)o * 768 + ch * 64 + (lane & 15) * 4);
        float m = fmaxf(fmaxf(fabsf(wv.x), fabsf(wv.y)), fmaxf(fabsf(wv.z), fabsf(wv.w)));
        #pragma unroll
        for (int s = 16; s; s >>= 1) m = fmaxf(m, __shfl_xor_sync(0xffffffffu, m, s));
        float sc, invw;
        if (m < 1e-30f) { sc = 0.f; invw = 0.f; }
        else            { sc = m * (1.f / 127.f); invw = 127.f / m; }
        if (lane < 16) {
            int word = (q8(wv.x * invw))
                     | (q8(wv.y * invw) << 8)
                     | (q8(wv.z * invw) << 16)
                     | (q8(wv.w * invw) << 24);
            g_wq2[(size_t)(ch * 16 + lane) * 768 + o] = word;
        }
        if (lane == 0) g_sb2[ch * 768 + o] = sc;
    }
}

// ---------------------------------------------------------------------------
// 2) GEMM1 int8 dp4a, 3-stage cp.async pipeline: 128v x 128o tile.
// ---------------------------------------------------------------------------
__global__ void __launch_bounds__(256, 2) gemm_qkv_kernel(
        const float* __restrict__ b_in) {
    __shared__ int As[3][16 * 128];
    __shared__ int Bs[3][16 * 128];
    const int tid = threadIdx.x;
    const int tx = tid & 15, ty = tid >> 4;
    const int n0 = blockIdx.y * 128;
    const int o0 = blockIdx.x * 128;
    const int t  = n0 >> 9;
    const int v0 = n0 & 511;
    const int lrow = tid >> 5;
    const int lcol = (tid & 31) * 4;

    float facc[8][8];
    #pragma unroll
    for (int p = 0; p < 8; p++)
        #pragma unroll
        for (int q = 0; q < 8; q++) facc[p][q] = 0.f;

    #pragma unroll
    for (int c0 = 0; c0 < 2; c0++) {
        #pragma unroll
        for (int r = 0; r < 2; r++) {
            int row = lrow + r * 8;
            cp16(&As[c0][row * 128 + lcol],
                 g_xq + ((size_t)t * 192 + c0 * 16 + row) * 512 + v0 + lcol);
            cp16(&Bs[c0][row * 128 + lcol],
                 g_wq + (size_t)(c0 * 16 + row) * 2304 + o0 + lcol);
        }
        asm volatile("cp.async.commit_group;" ::: "memory");
    }

    for (int ch = 0; ch < 12; ch++) {
        if (ch < 10) {
            const int ns = (ch + 2) % 3;
            const int kw0 = (ch + 2) * 16;
            #pragma unroll
            for (int r = 0; r < 2; r++) {
                int row = lrow + r * 8;
                cp16(&As[ns][row * 128 + lcol],
                     g_xq + ((size_t)t * 192 + kw0 + row) * 512 + v0 + lcol);
                cp16(&Bs[ns][row * 128 + lcol],
                     g_wq + (size_t)(kw0 + row) * 2304 + o0 + lcol);
            }
            asm volatile("cp.async.commit_group;" ::: "memory");
            asm volatile("cp.async.wait_group 2;" ::: "memory");
        } else if (ch == 10) {
            asm volatile("cp.async.wait_group 1;" ::: "memory");
        } else {
            asm volatile("cp.async.wait_group 0;" ::: "memory");
        }
        __syncthreads();
        const int st = ch % 3;

        const float sa = g_qa[t * 12 + ch];
        float ssb[8];
        #pragma unroll
        for (int g = 0; g < 2; g++)
            #pragma unroll
            for (int j = 0; j < 4; j++)
                ssb[g * 4 + j] = sa * g_sb[ch * 2304 + o0 + tx * 4 + j + 64 * g];

        #pragma unroll
        for (int h = 0; h < 2; h++) {
            int ia[8][4];
            #pragma unroll
            for (int p = 0; p < 8; p++)
                #pragma unroll
                for (int q = 0; q < 4; q++) ia[p][q] = 0;
            #pragma unroll
            for (int kw = 0; kw < 16; kw++) {
                int4 av = *(const int4*)&As[st][kw * 128 + ty * 4 + h * 64];
                int4 b0 = *(const int4*)&Bs[st][kw * 128 + tx * 4];
                int4 b1 = *(const int4*)&Bs[st][kw * 128 + tx * 4 + 64];
                int avv[4] = {av.x, av.y, av.z, av.w};
                int bov[8] = {b0.x, b0.y, b0.z, b0.w, b1.x, b1.y, b1.z, b1.w};
                #pragma unroll
                for (int p = 0; p < 8; p++)
                    #pragma unroll
                    for (int q = 0; q < 4; q++)
                        ia[p][q] = __dp4a(avv[q], bov[p], ia[p][q]);
            }
            #pragma unroll
            for (int p = 0; p < 8; p++)
                #pragma unroll
                for (int q = 0; q < 4; q++)
                    facc[p][h * 4 + q] = fmaf((float)ia[p][q], ssb[p], facc[p][h * 4 + q]);
        }
        __syncthreads();
    }

    float bi[8];
    #pragma unroll
    for (int g = 0; g < 2; g++)
        #pragma unroll
        for (int j = 0; j < 4; j++)
            bi[g * 4 + j] = b_in[o0 + tx * 4 + j + 64 * g];

    #pragma unroll
    for (int g = 0; g < 2; g++) {
        const int ob = o0 + tx * 4 + 64 * g;
        const int he = ob / 192;
        const int jj = ob - he * 192;
        const int part = jj >> 6;
        const int cb = jj & 63;
        float* dst = part == 0 ? g_q : (part == 1 ? g_k : g_v);
        #pragma unroll
        for (int h = 0; h < 2; h++)
            #pragma unroll
            for (int i2 = 0; i2 < 4; i2++) {
                int v = v0 + ty * 4 + i2 + 64 * h;
                float4 w;
                w.x = facc[g * 4 + 0][h * 4 + i2] + bi[g * 4 + 0];
                w.y = facc[g * 4 + 1][h * 4 + i2] + bi[g * 4 + 1];
                w.z = facc[g * 4 + 2][h * 4 + i2] + bi[g * 4 + 2];
                w.w = facc[g * 4 + 3][h * 4 + i2] + bi[g * 4 + 3];
                *(float4*)(dst + (((size_t)v * 12 + he) * 64 + t) * 64 + cb) = w;
            }
    }
}

// ---------------------------------------------------------------------------
// 3) T5 relative-position bias table
// ---------------------------------------------------------------------------
__global__ void bias_kernel(const float* __restrict__ emb) {
    const int t = blockIdx.x;
    const int s = threadIdx.x;
    int rel = t - s;
    int ret = rel < 0 ? 16 : 0;
    int n = rel < 0 ? -rel : rel;
    int b;
    if (n < 8) {
        b = n;
    } else {
        float f = logf((float)n / 8.0f);
        f = f / 2.772588722239781f;
        f = f * 8.0f;
        b = 8 + (int)f;
        if (b > 15) b = 15;
    }
    int bucket = ret + b;
    #pragma unroll
    for (int he = 0; he < 12; he++)
        g_bias[he * 4096 + t * 64 + s] = emb[bucket * 12 + he];
}

// ---------------------------------------------------------------------------
// 4) Attention with fused q/k LayerNorm; epilogue quantizes output for GEMM2.
// ---------------------------------------------------------------------------
__global__ void __launch_bounds__(256) attn_kernel(
        const float* __restrict__ qn_w, const float* __restrict__ qn_b,
        const float* __restrict__ kn_w, const float* __restrict__ kn_b) {
    __shared__ float sqv[64 * 64];
    __shared__ float skp[64 * 65];
    __shared__ float swts[4 * 64];   // qw, qb, kw, kb
    const int tid = threadIdx.x;
    const int blk = blockIdx.x;
    const int he = blk % 12;
    const int v  = blk / 12;
    const float* qb = g_q + (size_t)blk * 4096;
    const float* kb = g_k + (size_t)blk * 4096;

    if (tid < 64)        swts[tid]       = qn_w[tid];
    else if (tid < 128)  swts[tid]       = qn_b[tid - 64];
    else if (tid < 192)  swts[tid]       = kn_w[tid - 128];
    else                 swts[tid]       = kn_b[tid - 192];

    #pragma unroll
    for (int it = 0; it < 4; it++) {
        int i = tid * 4 + it * 1024;
        *(float4*)(sqv + i) = *(const float4*)(qb + i);
        float4 kv = *(const float4*)(kb + i);
        int s = i >> 6, c = i & 63;
        float* kd = skp + s * 65 + c;
        kd[0] = kv.x; kd[1] = kv.y; kd[2] = kv.z; kd[3] = kv.w;
    }
    __syncthreads();

    // fused LayerNorm on q and k rows: 4 threads per row, 16 cols each
    {
        const int r = tid >> 2;
        const int c0 = (tid & 3) * 16;
        #pragma unroll
        for (int which = 0; which < 2; which++) {
            float* row = which == 0 ? (sqv + r * 64) : (skp + r * 65);
            const float* wv = swts + which * 128;
            const float* bv = swts + which * 128 + 64;
            float xv[16];
            float s = 0.f, s2 = 0.f;
            #pragma unroll
            for (int j = 0; j < 16; j++) {
                xv[j] = row[c0 + j];
                s += xv[j];
                s2 += xv[j] * xv[j];
            }
            s  += __shfl_xor_sync(0xffffffffu, s, 1);
            s2 += __shfl_xor_sync(0xffffffffu, s2, 1);
            s  += __shfl_xor_sync(0xffffffffu, s, 2);
            s2 += __shfl_xor_sync(0xffffffffu, s2, 2);
            float mu = s * (1.f / 64.f);
            float var = s2 * (1.f / 64.f) - mu * mu;
            float inv = rsqrtf(var + 1e-5f);
            #pragma unroll
            for (int j = 0; j < 16; j++)
                row[c0 + j] = (xv[j] - mu) * inv * wv[c0 + j] + bv[c0 + j];
        }
    }
    __syncthreads();

    const int tx = tid & 15, ty = tid >> 4;
    const int t0 = ty * 4, s0 = tx * 4;
    float acc[4][4];
    #pragma unroll
    for (int i = 0; i < 4; i++)
        #pragma unroll
        for (int j = 0; j < 4; j++) acc[i][j] = 0.f;

    #pragma unroll 4
    for (int c = 0; c < 64; c++) {
        float a[4], b[4];
        #pragma unroll
        for (int i = 0; i < 4; i++) a[i] = sqv[(t0 + i) * 64 + c];
        #pragma unroll
        for (int j = 0; j < 4; j++) b[j] = skp[(s0 + j) * 65 + c];
        #pragma unroll
        for (int i = 0; i < 4; i++)
            #pragma unroll
            for (int j = 0; j < 4; j++)
                acc[i][j] = fmaf(a[i], b[j], acc[i][j]);
    }
    __syncthreads();

    const float* bb = g_bias + he * 4096;
    #pragma unroll
    for (int i = 0; i < 4; i++) {
        float4 bi = *(const float4*)(bb + (t0 + i) * 64 + s0);
        float4 pv;
        pv.x = fmaf(acc[i][0], 0.125f, bi.x);
        pv.y = fmaf(acc[i][1], 0.125f, bi.y);
        pv.z = fmaf(acc[i][2], 0.125f, bi.z);
        pv.w = fmaf(acc[i][3], 0.125f, bi.w);
        *(float4*)(skp + (t0 + i) * 64 + s0) = pv;
    }
    __syncthreads();

    const float* vb = g_v + (size_t)blk * 4096;
    #pragma unroll
    for (int it = 0; it < 4; it++) {
        int i = tid * 4 + it * 1024;
        *(float4*)(sqv + i) = *(const float4*)(vb + i);
    }

    {
        int r = tid >> 2, q = tid & 3;
        float* row = skp + r * 64;
        float mx = -1e30f;
        #pragma unroll
        for (int k = 0; k < 16; k++) mx = fmaxf(mx, row[q * 16 + k]);
        mx = fmaxf(mx, __shfl_xor_sync(0xffffffffu, mx, 1));
        mx = fmaxf(mx, __shfl_xor_sync(0xffffffffu, mx, 2));
        float e[16];
        float sum = 0.f;
        #pragma unroll
        for (int k = 0; k < 16; k++) {
            e[k] = expf(row[q * 16 + k] - mx);
            sum += e[k];
        }
        sum += __shfl_xor_sync(0xffffffffu, sum, 1);
        sum += __shfl_xor_sync(0xffffffffu, sum, 2);
        float rs = 1.f / sum;
        #pragma unroll
        for (int k = 0; k < 16; k++) row[q * 16 + k] = e[k] * rs;
    }
    __syncthreads();

    float oacc[4][4];
    #pragma unroll
    for (int i = 0; i < 4; i++)
        #pragma unroll
        for (int j = 0; j < 4; j++) oacc[i][j] = 0.f;

    #pragma unroll 4
    for (int s = 0; s < 64; s++) {
        float4 vv = *(const float4*)(sqv + s * 64 + tx * 4);
        #pragma unroll
        for (int i = 0; i < 4; i++) {
            float p = skp[(t0 + i) * 64 + s];
            oacc[i][0] = fmaf(p, vv.x, oacc[i][0]);
            oacc[i][1] = fmaf(p, vv.y, oacc[i][1]);
            oacc[i][2] = fmaf(p, vv.z, oacc[i][2]);
            oacc[i][3] = fmaf(p, vv.w, oacc[i][3]);
        }
    }

    // quantize per (n, head) row for GEMM2
    #pragma unroll
    for (int i = 0; i < 4; i++) {
        float m = fmaxf(fmaxf(fabsf(oacc[i][0]), fabsf(oacc[i][1])),
                        fmaxf(fabsf(oacc[i][2]), fabsf(oacc[i][3])));
        m = fmaxf(m, __shfl_xor_sync(0xffffffffu, m, 1));
        m = fmaxf(m, __shfl_xor_sync(0xffffffffu, m, 2));
        m = fmaxf(m, __shfl_xor_sync(0xffffffffu, m, 4));
        m = fmaxf(m, __shfl_xor_sync(0xffffffffu, m, 8));
        float invs = (m < 1e-30f) ? 0.f : 127.f / m;
        float scl  = (m < 1e-30f) ? 0.f : m * (1.f / 127.f);
        int w = q8(oacc[i][0] * invs)
              | (q8(oacc[i][1] * invs) << 8)
              | (q8(oacc[i][2] * invs) << 16)
              | (q8(oacc[i][3] * invs) << 24);
        int n = (t0 + i) * 512 + v;
        g_oq[(size_t)n * 192 + he * 16 + tx] = w;
        if (tx == 0) g_sa2[(size_t)n * 12 + he] = scl;
    }
}

// ---------------------------------------------------------------------------
// 5) GEMM2 int8 dp4a: out = x + gamma*(o @ w_out^T + b_out)
// ---------------------------------------------------------------------------
__global__ void __launch_bounds__(256, 2) gemm_out_kernel(
        const float* __restrict__ x,
        const float* __restrict__ b_out,
        const float* __restrict__ gamma,
        float* __restrict__ out) {
    __shared__ int As[2][16 * 128];
    __shared__ int Bs[2][16 * 128];
    __shared__ float ssa[12 * 128];
    __shared__ float ssbs[12 * 128];
    const int tid = threadIdx.x;
    const int tx = tid & 15, ty = tid >> 4;
    const int n0 = blockIdx.y * 128;
    const int o0 = blockIdx.x * 128;
    const int t  = n0 >> 9;
    const int v0 = n0 & 511;

    for (int i = tid; i < 1536; i += 256) {
        ssa[i]  = g_sa2[(size_t)(n0 + (i & 127)) * 12 + (i >> 7)];
        ssbs[i] = g_sb2[(i >> 7) * 768 + o0 + (i & 127)];
    }

    const int nl = tid & 127;
    const int half = tid >> 7;
    const int kwl = tid >> 4;
    const int ocl = (tid & 15) * 8;

    float facc[8][8];
    #pragma unroll
    for (int p = 0; p < 8; p++)
        #pragma unroll
        for (int q = 0; q < 8; q++) facc[p][q] = 0.f;

    int4 pa0, pa1, pb0, pb1;
    {
        const int* asrc = g_oq + (size_t)(n0 + nl) * 192 + half * 8;
        pa0 = *(const int4*)(asrc);
        pa1 = *(const int4*)(asrc + 4);
        const int* bsrc = g_wq2 + (size_t)kwl * 768 + o0 + ocl;
        pb0 = *(const int4*)(bsrc);
        pb1 = *(const int4*)(bsrc + 4);
    }
    {
        int base = half * 8;
        As[0][(base + 0) * 128 + nl] = pa0.x;
        As[0][(base + 1) * 128 + nl] = pa0.y;
        As[0][(base + 2) * 128 + nl] = pa0.z;
        As[0][(base + 3) * 128 + nl] = pa0.w;
        As[0][(base + 4) * 128 + nl] = pa1.x;
        As[0][(base + 5) * 128 + nl] = pa1.y;
        As[0][(base + 6) * 128 + nl] = pa1.z;
        As[0][(base + 7) * 128 + nl] = pa1.w;
        *(int4*)&Bs[0][kwl * 128 + ocl]     = pb0;
        *(int4*)&Bs[0][kwl * 128 + ocl + 4] = pb1;
    }
    __syncthreads();

    for (int ch = 0; ch < 12; ch++) {
        const int st = ch & 1;
        if (ch < 11) {
            const int kw0 = (ch + 1) * 16;
            const int* asrc = g_oq + (size_t)(n0 + nl) * 192 + kw0 + half * 8;
            pa0 = *(const int4*)(asrc);
            pa1 = *(const int4*)(asrc + 4);
            const int* bsrc = g_wq2 + (size_t)(kw0 + kwl) * 768 + o0 + ocl;
            pb0 = *(const int4*)(bsrc);
            pb1 = *(const int4*)(bsrc + 4);
        }

        float sbv[8];
        #pragma unroll
        for (int g = 0; g < 2; g++)
            #pragma unroll
            for (int j = 0; j < 4; j++)
                sbv[g * 4 + j] = ssbs[ch * 128 + tx * 4 + j + 64 * g];

        #pragma unroll
        for (int h = 0; h < 2; h++) {
            int ia[8][4];
            #pragma unroll
            for (int p = 0; p < 8; p++)
                #pragma unroll
                for (int q = 0; q < 4; q++) ia[p][q] = 0;
            #pragma unroll
            for (int kw = 0; kw < 16; kw++) {
                int4 av = *(const int4*)&As[st][kw * 128 + ty * 4 + h * 64];
                int4 b0 = *(const int4*)&Bs[st][kw * 128 + tx * 4];
                int4 b1 = *(const int4*)&Bs[st][kw * 128 + tx * 4 + 64];
                int avv[4] = {av.x, av.y, av.z, av.w};
                int bov[8] = {b0.x, b0.y, b0.z, b0.w, b1.x, b1.y, b1.z, b1.w};
                #pragma unroll
                for (int p = 0; p < 8; p++)
                    #pragma unroll
                    for (int q = 0; q < 4; q++)
                        ia[p][q] = __dp4a(avv[q], bov[p], ia[p][q]);
            }
            float sav[4];
            #pragma unroll
            for (int q = 0; q < 4; q++)
                sav[q] = ssa[ch * 128 + ty * 4 + q + 64 * h];
            #pragma unroll
            for (int p = 0; p < 8; p++)
                #pragma unroll
                for (int q = 0; q < 4; q++)
                    facc[p][h * 4 + q] = fmaf((float)ia[p][q], sbv[p] * sav[q],
                                              facc[p][h * 4 + q]);
        }

        if (ch < 11) {
            const int ns = st ^ 1;
            __syncthreads();
            int base = half * 8;
            As[ns][(base + 0) * 128 + nl] = pa0.x;
            As[ns][(base + 1) * 128 + nl] = pa0.y;
            As[ns][(base + 2) * 128 + nl] = pa0.z;
            As[ns][(base + 3) * 128 + nl] = pa0.w;
            As[ns][(base + 4) * 128 + nl] = pa1.x;
            As[ns][(base + 5) * 128 + nl] = pa1.y;
            As[ns][(base + 6) * 128 + nl] = pa1.z;
            As[ns][(base + 7) * 128 + nl] = pa1.w;
            *(int4*)&Bs[ns][kwl * 128 + ocl]     = pb0;
            *(int4*)&Bs[ns][kwl * 128 + ocl + 4] = pb1;
            __syncthreads();
        }
    }

    #pragma unroll
    for (int p = 0; p < 8; p++) {
        const int oc = o0 + tx * 4 + (p & 3) + 64 * (p >> 2);
        const float bo = b_out[oc];
        const float gm = gamma[oc];
        #pragma unroll
        for (int h = 0; h < 2; h++) {
            size_t base = (size_t)t * 393216 + (size_t)oc * 512 + v0 + ty * 4 + 64 * h;
            float4 xv = *(const float4*)(x + base);
            float4 w;
            w.x = xv.x + gm * (facc[p][h * 4 + 0] + bo);
            w.y = xv.y + gm * (facc[p][h * 4 + 1] + bo);
            w.z = xv.z + gm * (facc[p][h * 4 + 2] + bo);
            w.w = xv.w + gm * (facc[p][h * 4 + 3] + bo);
            *(float4*)(out + base) = w;
        }
    }
}

// ---------------------------------------------------------------------------
extern "C" void kernel_launch(void* const* d_in, const int* in_sizes, int n_in,
                              void* d_out, int out_size) {
    const float* x      = (const float*)d_in[0];
    const float* norm1w = (const float*)d_in[1];
    const float* w_in   = (const float*)d_in[2];
    const float* b_in   = (const float*)d_in[3];
    const float* qn_w   = (const float*)d_in[4];
    const float* qn_b   = (const float*)d_in[5];
    const float* kn_w   = (const float*)d_in[6];
    const float* kn_b   = (const float*)d_in[7];
    const float* rel    = (const float*)d_in[8];
    const float* w_out  = (const float*)d_in[9];
    const float* b_out  = (const float*)d_in[10];
    const float* gamma  = (const float*)d_in[11];
    float* out = (float*)d_out;

    gn_stats_kernel<<<768, 256>>>(x, norm1w);                  // 0
    quant_x_kernel<<<12288, 128>>>(x);                         // 1
    quant_w_kernel<<<288, 256>>>(w_in);                        // 2
    gemm_qkv_kernel<<<dim3(18, 256), 256>>>(b_in);             // 3 (profiled)
    quant_wout_kernel<<<96, 256>>>(w_out);                     // 4
    bias_kernel<<<64, 64>>>(rel);                              // 5
    attn_kernel<<<6144, 256>>>(qn_w, qn_b, kn_w, kn_b);        // 6
    gemm_out_kernel<<<dim3(6, 256), 256>>>(x, b_out, gamma, out);  // 7
}

// round 11
// speedup vs baseline: 1.3650x; 1.3650x over previous
#include <cuda_runtime.h>
#include <stdint.h>
#include <math.h>

// Shapes (fixed): T=64, B=1, C=768, V=H*W*D=512, heads=12, hd=64, M=T*V=32768

__device__ float g_scale[64 * 768];
__device__ float g_shift[64 * 768];
__device__ float g_qa[64 * 12];
__device__ float g_invqa[64 * 12];
__device__ float g_sb[12 * 2304];
__device__ int   g_xq[64 * 192 * 512];   // x int8 packed: [t][kw][v]
__device__ int   g_wq[192 * 2304];       // w_in int8 packed: [kw][o]
__device__ float g_bias[12 * 64 * 64];
__device__ float g_q[512 * 12 * 64 * 64];
__device__ float g_k[512 * 12 * 64 * 64];
__device__ float g_v[512 * 12 * 64 * 64];
__device__ int   g_oq[32768 * 192];      // attn out int8 packed: [n][kw]
__device__ float g_sa2[32768 * 12];      // attn out scale per (n, head)
__device__ int   g_wq2[192 * 768];       // w_out int8 packed: [kw][oc]
__device__ float g_sb2[12 * 768];        // w_out scale per (chunk, oc)

__device__ __forceinline__ void cp16(void* smem, const void* g) {
    unsigned int s = (unsigned int)__cvta_generic_to_shared(smem);
    asm volatile("cp.async.cg.shared.global [%0], [%1], 16;" :: "r"(s), "l"(g));
}
__device__ __forceinline__ int q8(float f) {
    int q = __float2int_rn(f);
    q = q > 127 ? 127 : q;
    q = q < -127 ? -127 : q;
    return q & 0xFF;
}

// ---------------------------------------------------------------------------
// 1) GroupNorm stats + per-(t,chunk) quant bounds
// ---------------------------------------------------------------------------
__global__ void gn_stats_kernel(const float* __restrict__ x,
                                const float* __restrict__ w) {
    const int t = blockIdx.x / 12;
    const int g = blockIdx.x % 12;
    const int tid = threadIdx.x;
    const int cl = tid >> 2;
    const int qq = tid & 3;
    const float* base = x + (size_t)t * 393216 + (size_t)(g * 64 + cl) * 512 + qq * 128;

    float s = 0.f, s2 = 0.f, mx = 0.f;
    #pragma unroll 8
    for (int i = 0; i < 32; i++) {
        float4 a = ((const float4*)base)[i];
        s  += a.x + a.y + a.z + a.w;
        s2 += a.x * a.x + a.y * a.y + a.z * a.z + a.w * a.w;
        mx = fmaxf(mx, fmaxf(fmaxf(fabsf(a.x), fabsf(a.y)), fmaxf(fabsf(a.z), fabsf(a.w))));
    }
    __shared__ float red[256], red2[256], rmax[256];
    red[tid] = s; red2[tid] = s2; rmax[tid] = mx;
    __syncthreads();
    for (int o = 128; o > 0; o >>= 1) {
        if (tid < o) {
            red[tid]  += red[tid + o];
            red2[tid] += red2[tid + o];
        }
        __syncthreads();
    }
    __shared__ float smu, sinv;
    if (tid == 0) {
        float mu  = red[0] * (1.f / 32768.f);
        float var = red2[0] * (1.f / 32768.f) - mu * mu;
        smu  = mu;
        sinv = rsqrtf(var + 1e-5f);
    }
    __syncthreads();
    const float mu = smu, inv = sinv;
    if (tid < 64) {
        float cm = fmaxf(fmaxf(rmax[tid * 4], rmax[tid * 4 + 1]),
                         fmaxf(rmax[tid * 4 + 2], rmax[tid * 4 + 3]));
        int c = g * 64 + tid;
        float sc = inv * w[c];
        g_scale[t * 768 + c] = sc;
        g_shift[t * 768 + c] = -mu * sc;
        red[tid] = fabsf(sc) * (cm + fabsf(mu));
    }
    __syncthreads();
    for (int o = 32; o > 0; o >>= 1) {
        if (tid < o && tid + o < 64) red[tid] = fmaxf(red[tid], red[tid + o]);
        __syncthreads();
    }
    if (tid == 0) {
        float bound = red[0];
        if (bound < 1e-30f) {
            g_qa[t * 12 + g] = 0.f;
            g_invqa[t * 12 + g] = 0.f;
        } else {
            g_qa[t * 12 + g] = bound * (1.f / 127.f);
            g_invqa[t * 12 + g] = 127.f / bound;
        }
    }
}

// ---------------------------------------------------------------------------
// 1b) quantize + k-pack xn -> g_xq[t][kw][v]
// ---------------------------------------------------------------------------
__global__ void __launch_bounds__(128) quant_x_kernel(const float* __restrict__ x) {
    const int b = blockIdx.x;
    const int t = b / 192;
    const int kw = b % 192;
    const int ch = kw >> 4;
    const int tid = threadIdx.x;
    const float qinv = g_invqa[t * 12 + ch];
    const int c0 = kw * 4;

    int w[4] = {0, 0, 0, 0};
    #pragma unroll
    for (int r = 0; r < 4; r++) {
        int c = c0 + r;
        float scm = g_scale[t * 768 + c] * qinv;
        float shm = g_shift[t * 768 + c] * qinv;
        float4 f = *(const float4*)(x + (size_t)t * 393216 + (size_t)c * 512 + tid * 4);
        w[0] |= q8(fmaf(f.x, scm, shm)) << (8 * r);
        w[1] |= q8(fmaf(f.y, scm, shm)) << (8 * r);
        w[2] |= q8(fmaf(f.z, scm, shm)) << (8 * r);
        w[3] |= q8(fmaf(f.w, scm, shm)) << (8 * r);
    }
    *(int4*)(g_xq + ((size_t)t * 192 + kw) * 512 + tid * 4) = make_int4(w[0], w[1], w[2], w[3]);
}

// ---------------------------------------------------------------------------
// 1c) quantize w_in -> g_wq[kw][o], g_sb[ch][o]
// ---------------------------------------------------------------------------
__global__ void __launch_bounds__(256) quant_w_kernel(const float* __restrict__ w_in) {
    const int o = blockIdx.x * 8 + (threadIdx.x >> 5);
    const int lane = threadIdx.x & 31;
    #pragma unroll
    for (int ch = 0; ch < 12; ch++) {
        float4 wv = *(const float4*)(w_in + (size_t)o * 768 + ch * 64 + (lane & 15) * 4);
        float m = fmaxf(fmaxf(fabsf(wv.x), fabsf(wv.y)), fmaxf(fabsf(wv.z), fabsf(wv.w)));
        #pragma unroll
        for (int s = 16; s; s >>= 1) m = fmaxf(m, __shfl_xor_sync(0xffffffffu, m, s));
        float sc, invw;
        if (m < 1e-30f) { sc = 0.f; invw = 0.f; }
        else            { sc = m * (1.f / 127.f); invw = 127.f / m; }
        if (lane < 16) {
            int word = (q8(wv.x * invw))
                     | (q8(wv.y * invw) << 8)
                     | (q8(wv.z * invw) << 16)
                     | (q8(wv.w * invw) << 24);
            g_wq[(size_t)(ch * 16 + lane) * 2304 + o] = word;
        }
        if (lane == 0) g_sb[ch * 2304 + o] = sc;
    }
}

// ---------------------------------------------------------------------------
// 1d) quantize w_out -> g_wq2[kw][oc], g_sb2[ch][oc]
// ---------------------------------------------------------------------------
__global__ void __launch_bounds__(256) quant_wout_kernel(const float* __restrict__ w_out) {
    const int o = blockIdx.x * 8 + (threadIdx.x >> 5);
    const int lane = threadIdx.x & 31;
    #pragma unroll
    for (int ch = 0; ch < 12; ch++) {
        float4 wv = *(const float4*)(w_out + (size_t)o * 768 + ch * 64 + (lane & 15) * 4);
        float m = fmaxf(fmaxf(fabsf(wv.x), fabsf(wv.y)), fmaxf(fabsf(wv.z), fabsf(wv.w)));
        #pragma unroll
        for (int s = 16; s; s >>= 1) m = fmaxf(m, __shfl_xor_sync(0xffffffffu, m, s));
        float sc, invw;
        if (m < 1e-30f) { sc = 0.f; invw = 0.f; }
        else            { sc = m * (1.f / 127.f); invw = 127.f / m; }
        if (lane < 16) {
            int word = (q8(wv.x * invw))
                     | (q8(wv.y * invw) << 8)
                     | (q8(wv.z * invw) << 16)
                     | (q8(wv.w * invw) << 24);
            g_wq2[(size_t)(ch * 16 + lane) * 768 + o] = word;
        }
        if (lane == 0) g_sb2[ch * 768 + o] = sc;
    }
}

// ---------------------------------------------------------------------------
// 2) GEMM1 int8 dp4a (R9 2-stage version): 128v x 128o tile.
// ---------------------------------------------------------------------------
__global__ void __launch_bounds__(256, 2) gemm_qkv_kernel(
        const float* __restrict__ b_in) {
    __shared__ int As[2][16 * 128];
    __shared__ int Bs[2][16 * 128];
    const int tid = threadIdx.x;
    const int tx = tid & 15, ty = tid >> 4;
    const int n0 = blockIdx.y * 128;
    const int o0 = blockIdx.x * 128;
    const int t  = n0 >> 9;
    const int v0 = n0 & 511;
    const int lrow = tid >> 5;
    const int lcol = (tid & 31) * 4;

    float facc[8][8];
    #pragma unroll
    for (int p = 0; p < 8; p++)
        #pragma unroll
        for (int q = 0; q < 8; q++) facc[p][q] = 0.f;

    #pragma unroll
    for (int r = 0; r < 2; r++) {
        int row = lrow + r * 8;
        cp16(&As[0][row * 128 + lcol], g_xq + ((size_t)t * 192 + row) * 512 + v0 + lcol);
        cp16(&Bs[0][row * 128 + lcol], g_wq + (size_t)row * 2304 + o0 + lcol);
    }
    asm volatile("cp.async.commit_group;" ::: "memory");

    for (int ch = 0; ch < 12; ch++) {
        if (ch < 11) {
            const int ns = (ch + 1) & 1;
            const int kw0 = (ch + 1) * 16;
            #pragma unroll
            for (int r = 0; r < 2; r++) {
                int row = lrow + r * 8;
                cp16(&As[ns][row * 128 + lcol],
                     g_xq + ((size_t)t * 192 + kw0 + row) * 512 + v0 + lcol);
                cp16(&Bs[ns][row * 128 + lcol],
                     g_wq + (size_t)(kw0 + row) * 2304 + o0 + lcol);
            }
            asm volatile("cp.async.commit_group;" ::: "memory");
            asm volatile("cp.async.wait_group 1;" ::: "memory");
        } else {
            asm volatile("cp.async.wait_group 0;" ::: "memory");
        }
        __syncthreads();
        const int st = ch & 1;

        const float sa = g_qa[t * 12 + ch];
        float ssb[8];
        #pragma unroll
        for (int g = 0; g < 2; g++)
            #pragma unroll
            for (int j = 0; j < 4; j++)
                ssb[g * 4 + j] = sa * g_sb[ch * 2304 + o0 + tx * 4 + j + 64 * g];

        #pragma unroll
        for (int h = 0; h < 2; h++) {
            int ia[8][4];
            #pragma unroll
            for (int p = 0; p < 8; p++)
                #pragma unroll
                for (int q = 0; q < 4; q++) ia[p][q] = 0;
            #pragma unroll
            for (int kw = 0; kw < 16; kw++) {
                int4 av = *(const int4*)&As[st][kw * 128 + ty * 4 + h * 64];
                int4 b0 = *(const int4*)&Bs[st][kw * 128 + tx * 4];
                int4 b1 = *(const int4*)&Bs[st][kw * 128 + tx * 4 + 64];
                int avv[4] = {av.x, av.y, av.z, av.w};
                int bov[8] = {b0.x, b0.y, b0.z, b0.w, b1.x, b1.y, b1.z, b1.w};
                #pragma unroll
                for (int p = 0; p < 8; p++)
                    #pragma unroll
                    for (int q = 0; q < 4; q++)
                        ia[p][q] = __dp4a(avv[q], bov[p], ia[p][q]);
            }
            #pragma unroll
            for (int p = 0; p < 8; p++)
                #pragma unroll
                for (int q = 0; q < 4; q++)
                    facc[p][h * 4 + q] = fmaf((float)ia[p][q], ssb[p], facc[p][h * 4 + q]);
        }
        __syncthreads();
    }

    float bi[8];
    #pragma unroll
    for (int g = 0; g < 2; g++)
        #pragma unroll
        for (int j = 0; j < 4; j++)
            bi[g * 4 + j] = b_in[o0 + tx * 4 + j + 64 * g];

    #pragma unroll
    for (int g = 0; g < 2; g++) {
        const int ob = o0 + tx * 4 + 64 * g;
        const int he = ob / 192;
        const int jj = ob - he * 192;
        const int part = jj >> 6;
        const int cb = jj & 63;
        float* dst = part == 0 ? g_q : (part == 1 ? g_k : g_v);
        #pragma unroll
        for (int h = 0; h < 2; h++)
            #pragma unroll
            for (int i2 = 0; i2 < 4; i2++) {
                int v = v0 + ty * 4 + i2 + 64 * h;
                float4 w;
                w.x = facc[g * 4 + 0][h * 4 + i2] + bi[g * 4 + 0];
                w.y = facc[g * 4 + 1][h * 4 + i2] + bi[g * 4 + 1];
                w.z = facc[g * 4 + 2][h * 4 + i2] + bi[g * 4 + 2];
                w.w = facc[g * 4 + 3][h * 4 + i2] + bi[g * 4 + 3];
                *(float4*)(dst + (((size_t)v * 12 + he) * 64 + t) * 64 + cb) = w;
            }
    }
}

// ---------------------------------------------------------------------------
// 3) T5 relative-position bias table
// ---------------------------------------------------------------------------
__global__ void bias_kernel(const float* __restrict__ emb) {
    const int t = blockIdx.x;
    const int s = threadIdx.x;
    int rel = t - s;
    int ret = rel < 0 ? 16 : 0;
    int n = rel < 0 ? -rel : rel;
    int b;
    if (n < 8) {
        b = n;
    } else {
        float f = logf((float)n / 8.0f);
        f = f / 2.772588722239781f;
        f = f * 8.0f;
        b = 8 + (int)f;
        if (b > 15) b = 15;
    }
    int bucket = ret + b;
    #pragma unroll
    for (int he = 0; he < 12; he++)
        g_bias[he * 4096 + t * 64 + s] = emb[bucket * 12 + he];
}

// ---------------------------------------------------------------------------
// 4) Attention with register-fused q/k LayerNorm (conflict-free):
//    LN is computed during the load phase; 16 consecutive lanes own one row,
//    each lane 4 consecutive channels -> shfl_xor 1/2/4/8 reduces sum/sumsq.
// ---------------------------------------------------------------------------
__global__ void __launch_bounds__(256) attn_kernel(
        const float* __restrict__ qn_w, const float* __restrict__ qn_b,
        const float* __restrict__ kn_w, const float* __restrict__ kn_b) {
    __shared__ float sqv[64 * 64];
    __shared__ float skp[64 * 65];
    const int tid = threadIdx.x;
    const int blk = blockIdx.x;
    const int he = blk % 12;
    const int v  = blk / 12;
    const float* qb = g_q + (size_t)blk * 4096;
    const float* kb = g_k + (size_t)blk * 4096;
    const int c0 = (tid & 15) * 4;   // channel base this lane owns

    // LN weights for the 4 channels this lane touches (broadcast L1/const)
    const float4 qw4 = *(const float4*)(qn_w + c0);
    const float4 qb4 = *(const float4*)(qn_b + c0);
    const float4 kw4 = *(const float4*)(kn_w + c0);
    const float4 kb4 = *(const float4*)(kn_b + c0);

    #pragma unroll
    for (int it = 0; it < 4; it++) {
        int i = tid * 4 + it * 1024;      // row = i>>6, col = c0
        int r = i >> 6;
        // ---- q: load, LN in registers, store ----
        float4 qv = *(const float4*)(qb + i);
        {
            float s  = qv.x + qv.y + qv.z + qv.w;
            float s2 = qv.x * qv.x + qv.y * qv.y + qv.z * qv.z + qv.w * qv.w;
            s  += __shfl_xor_sync(0xffffffffu, s, 1);
            s2 += __shfl_xor_sync(0xffffffffu, s2, 1);
            s  += __shfl_xor_sync(0xffffffffu, s, 2);
            s2 += __shfl_xor_sync(0xffffffffu, s2, 2);
            s  += __shfl_xor_sync(0xffffffffu, s, 4);
            s2 += __shfl_xor_sync(0xffffffffu, s2, 4);
            s  += __shfl_xor_sync(0xffffffffu, s, 8);
            s2 += __shfl_xor_sync(0xffffffffu, s2, 8);
            float mu  = s * (1.f / 64.f);
            float var = s2 * (1.f / 64.f) - mu * mu;
            float inv = rsqrtf(var + 1e-5f);
            qv.x = (qv.x - mu) * inv * qw4.x + qb4.x;
            qv.y = (qv.y - mu) * inv * qw4.y + qb4.y;
            qv.z = (qv.z - mu) * inv * qw4.z + qb4.z;
            qv.w = (qv.w - mu) * inv * qw4.w + qb4.w;
        }
        *(float4*)(sqv + i) = qv;
        // ---- k: load, LN in registers, store (pitch 65) ----
        float4 kv = *(const float4*)(kb + i);
        {
            float s  = kv.x + kv.y + kv.z + kv.w;
            float s2 = kv.x * kv.x + kv.y * kv.y + kv.z * kv.z + kv.w * kv.w;
            s  += __shfl_xor_sync(0xffffffffu, s, 1);
            s2 += __shfl_xor_sync(0xffffffffu, s2, 1);
            s  += __shfl_xor_sync(0xffffffffu, s, 2);
            s2 += __shfl_xor_sync(0xffffffffu, s2, 2);
            s  += __shfl_xor_sync(0xffffffffu, s, 4);
            s2 += __shfl_xor_sync(0xffffffffu, s2, 4);
            s  += __shfl_xor_sync(0xffffffffu, s, 8);
            s2 += __shfl_xor_sync(0xffffffffu, s2, 8);
            float mu  = s * (1.f / 64.f);
            float var = s2 * (1.f / 64.f) - mu * mu;
            float inv = rsqrtf(var + 1e-5f);
            kv.x = (kv.x - mu) * inv * kw4.x + kb4.x;
            kv.y = (kv.y - mu) * inv * kw4.y + kb4.y;
            kv.z = (kv.z - mu) * inv * kw4.z + kb4.z;
            kv.w = (kv.w - mu) * inv * kw4.w + kb4.w;
        }
        float* kd = skp + r * 65 + c0;
        kd[0] = kv.x; kd[1] = kv.y; kd[2] = kv.z; kd[3] = kv.w;
    }
    __syncthreads();

    const int tx = tid & 15, ty = tid >> 4;
    const int t0 = ty * 4, s0 = tx * 4;
    float acc[4][4];
    #pragma unroll
    for (int i = 0; i < 4; i++)
        #pragma unroll
        for (int j = 0; j < 4; j++) acc[i][j] = 0.f;

    #pragma unroll 4
    for (int c = 0; c < 64; c++) {
        float a[4], b[4];
        #pragma unroll
        for (int i = 0; i < 4; i++) a[i] = sqv[(t0 + i) * 64 + c];
        #pragma unroll
        for (int j = 0; j < 4; j++) b[j] = skp[(s0 + j) * 65 + c];
        #pragma unroll
        for (int i = 0; i < 4; i++)
            #pragma unroll
            for (int j = 0; j < 4; j++)
                acc[i][j] = fmaf(a[i], b[j], acc[i][j]);
    }
    __syncthreads();

    const float* bb = g_bias + he * 4096;
    #pragma unroll
    for (int i = 0; i < 4; i++) {
        float4 bi = *(const float4*)(bb + (t0 + i) * 64 + s0);
        float4 pv;
        pv.x = fmaf(acc[i][0], 0.125f, bi.x);
        pv.y = fmaf(acc[i][1], 0.125f, bi.y);
        pv.z = fmaf(acc[i][2], 0.125f, bi.z);
        pv.w = fmaf(acc[i][3], 0.125f, bi.w);
        *(float4*)(skp + (t0 + i) * 64 + s0) = pv;
    }
    __syncthreads();

    const float* vb = g_v + (size_t)blk * 4096;
    #pragma unroll
    for (int it = 0; it < 4; it++) {
        int i = tid * 4 + it * 1024;
        *(float4*)(sqv + i) = *(const float4*)(vb + i);
    }

    {
        int r = tid >> 2, q = tid & 3;
        float* row = skp + r * 64;
        float mx = -1e30f;
        #pragma unroll
        for (int k = 0; k < 16; k++) mx = fmaxf(mx, row[q * 16 + k]);
        mx = fmaxf(mx, __shfl_xor_sync(0xffffffffu, mx, 1));
        mx = fmaxf(mx, __shfl_xor_sync(0xffffffffu, mx, 2));
        float e[16];
        float sum = 0.f;
        #pragma unroll
        for (int k = 0; k < 16; k++) {
            e[k] = expf(row[q * 16 + k] - mx);
            sum += e[k];
        }
        sum += __shfl_xor_sync(0xffffffffu, sum, 1);
        sum += __shfl_xor_sync(0xffffffffu, sum, 2);
        float rs = 1.f / sum;
        #pragma unroll
        for (int k = 0; k < 16; k++) row[q * 16 + k] = e[k] * rs;
    }
    __syncthreads();

    float oacc[4][4];
    #pragma unroll
    for (int i = 0; i < 4; i++)
        #pragma unroll
        for (int j = 0; j < 4; j++) oacc[i][j] = 0.f;

    #pragma unroll 4
    for (int s = 0; s < 64; s++) {
        float4 vv = *(const float4*)(sqv + s * 64 + tx * 4);
        #pragma unroll
        for (int i = 0; i < 4; i++) {
            float p = skp[(t0 + i) * 64 + s];
            oacc[i][0] = fmaf(p, vv.x, oacc[i][0]);
            oacc[i][1] = fmaf(p, vv.y, oacc[i][1]);
            oacc[i][2] = fmaf(p, vv.z, oacc[i][2]);
            oacc[i][3] = fmaf(p, vv.w, oacc[i][3]);
        }
    }

    // quantize per (n, head) row for GEMM2
    #pragma unroll
    for (int i = 0; i < 4; i++) {
        float m = fmaxf(fmaxf(fabsf(oacc[i][0]), fabsf(oacc[i][1])),
                        fmaxf(fabsf(oacc[i][2]), fabsf(oacc[i][3])));
        m = fmaxf(m, __shfl_xor_sync(0xffffffffu, m, 1));
        m = fmaxf(m, __shfl_xor_sync(0xffffffffu, m, 2));
        m = fmaxf(m, __shfl_xor_sync(0xffffffffu, m, 4));
        m = fmaxf(m, __shfl_xor_sync(0xffffffffu, m, 8));
        float invs = (m < 1e-30f) ? 0.f : 127.f / m;
        float scl  = (m < 1e-30f) ? 0.f : m * (1.f / 127.f);
        int w = q8(oacc[i][0] * invs)
              | (q8(oacc[i][1] * invs) << 8)
              | (q8(oacc[i][2] * invs) << 16)
              | (q8(oacc[i][3] * invs) << 24);
        int n = (t0 + i) * 512 + v;
        g_oq[(size_t)n * 192 + he * 16 + tx] = w;
        if (tx == 0) g_sa2[(size_t)n * 12 + he] = scl;
    }
}

// ---------------------------------------------------------------------------
// 5) GEMM2 int8 dp4a (R9 version): out = x + gamma*(o @ w_out^T + b_out)
// ---------------------------------------------------------------------------
__global__ void __launch_bounds__(256, 2) gemm_out_kernel(
        const float* __restrict__ x,
        const float* __restrict__ b_out,
        const float* __restrict__ gamma,
        float* __restrict__ out) {
    __shared__ int As[2][16 * 128];
    __shared__ int Bs[2][16 * 128];
    __shared__ float ssa[12 * 128];
    __shared__ float ssbs[12 * 128];
    const int tid = threadIdx.x;
    const int tx = tid & 15, ty = tid >> 4;
    const int n0 = blockIdx.y * 128;
    const int o0 = blockIdx.x * 128;
    const int t  = n0 >> 9;
    const int v0 = n0 & 511;

    for (int i = tid; i < 1536; i += 256) {
        ssa[i]  = g_sa2[(size_t)(n0 + (i & 127)) * 12 + (i >> 7)];
        ssbs[i] = g_sb2[(i >> 7) * 768 + o0 + (i & 127)];
    }

    const int nl = tid & 127;
    const int half = tid >> 7;
    const int kwl = tid >> 4;
    const int ocl = (tid & 15) * 8;

    float facc[8][8];
    #pragma unroll
    for (int p = 0; p < 8; p++)
        #pragma unroll
        for (int q = 0; q < 8; q++) facc[p][q] = 0.f;

    int4 pa0, pa1, pb0, pb1;
    {
        const int* asrc = g_oq + (size_t)(n0 + nl) * 192 + half * 8;
        pa0 = *(const int4*)(asrc);
        pa1 = *(const int4*)(asrc + 4);
        const int* bsrc = g_wq2 + (size_t)kwl * 768 + o0 + ocl;
        pb0 = *(const int4*)(bsrc);
        pb1 = *(const int4*)(bsrc + 4);
    }
    {
        int base = half * 8;
        As[0][(base + 0) * 128 + nl] = pa0.x;
        As[0][(base + 1) * 128 + nl] = pa0.y;
        As[0][(base + 2) * 128 + nl] = pa0.z;
        As[0][(base + 3) * 128 + nl] = pa0.w;
        As[0][(base + 4) * 128 + nl] = pa1.x;
        As[0][(base + 5) * 128 + nl] = pa1.y;
        As[0][(base + 6) * 128 + nl] = pa1.z;
        As[0][(base + 7) * 128 + nl] = pa1.w;
        *(int4*)&Bs[0][kwl * 128 + ocl]     = pb0;
        *(int4*)&Bs[0][kwl * 128 + ocl + 4] = pb1;
    }
    __syncthreads();

    for (int ch = 0; ch < 12; ch++) {
        const int st = ch & 1;
        if (ch < 11) {
            const int kw0 = (ch + 1) * 16;
            const int* asrc = g_oq + (size_t)(n0 + nl) * 192 + kw0 + half * 8;
            pa0 = *(const int4*)(asrc);
            pa1 = *(const int4*)(asrc + 4);
            const int* bsrc = g_wq2 + (size_t)(kw0 + kwl) * 768 + o0 + ocl;
            pb0 = *(const int4*)(bsrc);
            pb1 = *(const int4*)(bsrc + 4);
        }

        float sbv[8];
        #pragma unroll
        for (int g = 0; g < 2; g++)
            #pragma unroll
            for (int j = 0; j < 4; j++)
                sbv[g * 4 + j] = ssbs[ch * 128 + tx * 4 + j + 64 * g];

        #pragma unroll
        for (int h = 0; h < 2; h++) {
            int ia[8][4];
            #pragma unroll
            for (int p = 0; p < 8; p++)
                #pragma unroll
                for (int q = 0; q < 4; q++) ia[p][q] = 0;
            #pragma unroll
            for (int kw = 0; kw < 16; kw++) {
                int4 av = *(const int4*)&As[st][kw * 128 + ty * 4 + h * 64];
                int4 b0 = *(const int4*)&Bs[st][kw * 128 + tx * 4];
                int4 b1 = *(const int4*)&Bs[st][kw * 128 + tx * 4 + 64];
                int avv[4] = {av.x, av.y, av.z, av.w};
                int bov[8] = {b0.x, b0.y, b0.z, b0.w, b1.x, b1.y, b1.z, b1.w};
                #pragma unroll
                for (int p = 0; p < 8; p++)
                    #pragma unroll
                    for (int q = 0; q < 4; q++)
                        ia[p][q] = __dp4a(avv[q], bov[p], ia[p][q]);
            }
            float sav[4];
            #pragma unroll
            for (int q = 0; q < 4; q++)
                sav[q] = ssa[ch * 128 + ty * 4 + q + 64 * h];
            #pragma unroll
            for (int p = 0; p < 8; p++)
                #pragma unroll
                for (int q = 0; q < 4; q++)
                    facc[p][h * 4 + q] = fmaf((float)ia[p][q], sbv[p] * sav[q],
                                              facc[p][h * 4 + q]);
        }

        if (ch < 11) {
            const int ns = st ^ 1;
            __syncthreads();
            int base = half * 8;
            As[ns][(base + 0) * 128 + nl] = pa0.x;
            As[ns][(base + 1) * 128 + nl] = pa0.y;
            As[ns][(base + 2) * 128 + nl] = pa0.z;
            As[ns][(base + 3) * 128 + nl] = pa0.w;
            As[ns][(base + 4) * 128 + nl] = pa1.x;
            As[ns][(base + 5) * 128 + nl] = pa1.y;
            As[ns][(base + 6) * 128 + nl] = pa1.z;
            As[ns][(base + 7) * 128 + nl] = pa1.w;
            *(int4*)&Bs[ns][kwl * 128 + ocl]     = pb0;
            *(int4*)&Bs[ns][kwl * 128 + ocl + 4] = pb1;
            __syncthreads();
        }
    }

    #pragma unroll
    for (int p = 0; p < 8; p++) {
        const int oc = o0 + tx * 4 + (p & 3) + 64 * (p >> 2);
        const float bo = b_out[oc];
        const float gm = gamma[oc];
        #pragma unroll
        for (int h = 0; h < 2; h++) {
            size_t base = (size_t)t * 393216 + (size_t)oc * 512 + v0 + ty * 4 + 64 * h;
            float4 xv = *(const float4*)(x + base);
            float4 w;
            w.x = xv.x + gm * (facc[p][h * 4 + 0] + bo);
            w.y = xv.y + gm * (facc[p][h * 4 + 1] + bo);
            w.z = xv.z + gm * (facc[p][h * 4 + 2] + bo);
            w.w = xv.w + gm * (facc[p][h * 4 + 3] + bo);
            *(float4*)(out + base) = w;
        }
    }
}

// ---------------------------------------------------------------------------
extern "C" void kernel_launch(void* const* d_in, const int* in_sizes, int n_in,
                              void* d_out, int out_size) {
    const float* x      = (const float*)d_in[0];
    const float* norm1w = (const float*)d_in[1];
    const float* w_in   = (const float*)d_in[2];
    const float* b_in   = (const float*)d_in[3];
    const float* qn_w   = (const float*)d_in[4];
    const float* qn_b   = (const float*)d_in[5];
    const float* kn_w   = (const float*)d_in[6];
    const float* kn_b   = (const float*)d_in[7];
    const float* rel    = (const float*)d_in[8];
    const float* w_out  = (const float*)d_in[9];
    const float* b_out  = (const float*)d_in[10];
    const float* gamma  = (const float*)d_in[11];
    float* out = (float*)d_out;

    gn_stats_kernel<<<768, 256>>>(x, norm1w);                  // 0
    quant_x_kernel<<<12288, 128>>>(x);                         // 1
    quant_w_kernel<<<288, 256>>>(w_in);                        // 2
    gemm_qkv_kernel<<<dim3(18, 256), 256>>>(b_in);             // 3 (profiled)
    quant_wout_kernel<<<96, 256>>>(w_out);                     // 4
    bias_kernel<<<64, 64>>>(rel);                              // 5
    attn_kernel<<<6144, 256>>>(qn_w, qn_b, kn_w, kn_b);        // 6
    gemm_out_kernel<<<dim3(6, 256), 256>>>(x, b_out, gamma, out);  // 7
}

// round 12
// speedup vs baseline: 1.3763x; 1.0083x over previous
#include <cuda_runtime.h>
#include <stdint.h>
#include <math.h>

// Shapes (fixed): T=64, B=1, C=768, V=H*W*D=512, heads=12, hd=64, M=T*V=32768

__device__ float g_qa[64 * 12];
__device__ float g_sb[12 * 2304];
__device__ int   g_xq[64 * 192 * 512];   // x int8 packed: [t][kw][v]
__device__ int   g_wq[192 * 2304];       // w_in int8 packed: [kw][o]
__device__ float g_bias[12 * 64 * 64];
__device__ float g_q[512 * 12 * 64 * 64];
__device__ float g_k[512 * 12 * 64 * 64];
__device__ float g_v[512 * 12 * 64 * 64];
__device__ int   g_oq[32768 * 192];      // attn out int8 packed: [n][kw]
__device__ float g_sa2[32768 * 12];      // attn out scale per (n, head)
__device__ int   g_wq2[192 * 768];       // w_out int8 packed: [kw][oc]
__device__ float g_sb2[12 * 768];        // w_out scale per (chunk, oc)

__device__ __forceinline__ void cp16(void* smem, const void* g) {
    unsigned int s = (unsigned int)__cvta_generic_to_shared(smem);
    asm volatile("cp.async.cg.shared.global [%0], [%1], 16;" :: "r"(s), "l"(g));
}
__device__ __forceinline__ int q8(float f) {
    int q = __float2int_rn(f);
    q = q > 127 ? 127 : q;
    q = q < -127 ? -127 : q;
    return q & 0xFF;
}

// ---------------------------------------------------------------------------
// 1) GroupNorm stats + per-(t,chunk) quant bound + fused x quantization.
//    block = (t, g). After stats, the same block quantizes its 64ch x 512vox
//    slice into g_xq (x re-read is L2-hot).
// ---------------------------------------------------------------------------
__global__ void gn_stats_quant_kernel(const float* __restrict__ x,
                                      const float* __restrict__ w) {
    const int t = blockIdx.x / 12;
    const int g = blockIdx.x % 12;
    const int tid = threadIdx.x;
    const int cl = tid >> 2;
    const int qq = tid & 3;
    const float* base = x + (size_t)t * 393216 + (size_t)(g * 64 + cl) * 512 + qq * 128;

    float s = 0.f, s2 = 0.f, mx = 0.f;
    #pragma unroll 8
    for (int i = 0; i < 32; i++) {
        float4 a = ((const float4*)base)[i];
        s  += a.x + a.y + a.z + a.w;
        s2 += a.x * a.x + a.y * a.y + a.z * a.z + a.w * a.w;
        mx = fmaxf(mx, fmaxf(fmaxf(fabsf(a.x), fabsf(a.y)), fmaxf(fabsf(a.z), fabsf(a.w))));
    }
    __shared__ float red[256], red2[256], rmax[256];
    __shared__ float sscale[64], sshift[64];
    __shared__ float sqinv;
    red[tid] = s; red2[tid] = s2; rmax[tid] = mx;
    __syncthreads();
    for (int o = 128; o > 0; o >>= 1) {
        if (tid < o) {
            red[tid]  += red[tid + o];
            red2[tid] += red2[tid + o];
        }
        __syncthreads();
    }
    __shared__ float smu, sinv;
    if (tid == 0) {
        float mu  = red[0] * (1.f / 32768.f);
        float var = red2[0] * (1.f / 32768.f) - mu * mu;
        smu  = mu;
        sinv = rsqrtf(var + 1e-5f);
    }
    __syncthreads();
    const float mu = smu, inv = sinv;
    if (tid < 64) {
        float cm = fmaxf(fmaxf(rmax[tid * 4], rmax[tid * 4 + 1]),
                         fmaxf(rmax[tid * 4 + 2], rmax[tid * 4 + 3]));
        int c = g * 64 + tid;
        float sc = inv * w[c];
        sscale[tid] = sc;
        sshift[tid] = -mu * sc;
        red[tid] = fabsf(sc) * (cm + fabsf(mu));
    }
    __syncthreads();
    for (int o = 32; o > 0; o >>= 1) {
        if (tid < o && tid + o < 64) red[tid] = fmaxf(red[tid], red[tid + o]);
        __syncthreads();
    }
    if (tid == 0) {
        float bound = red[0];
        if (bound < 1e-30f) {
            g_qa[t * 12 + g] = 0.f;
            sqinv = 0.f;
        } else {
            g_qa[t * 12 + g] = bound * (1.f / 127.f);
            sqinv = 127.f / bound;
        }
    }
    __syncthreads();

    // fused quantization: 16 kw rows x 512 voxels -> g_xq[t][g*16+kwl][v]
    const float qinv = sqinv;
    const float* xg = x + (size_t)t * 393216 + (size_t)g * 64 * 512;
    for (int i = tid; i < 2048; i += 256) {
        int kwl = i >> 7;            // 0..15
        int vb  = (i & 127) * 4;     // voxel base
        int c0  = kwl * 4;           // local channel base
        int wd[4] = {0, 0, 0, 0};
        #pragma unroll
        for (int r = 0; r < 4; r++) {
            int c = c0 + r;
            float scm = sscale[c] * qinv;
            float shm = sshift[c] * qinv;
            float4 f = *(const float4*)(xg + (size_t)c * 512 + vb);
            wd[0] |= q8(fmaf(f.x, scm, shm)) << (8 * r);
            wd[1] |= q8(fmaf(f.y, scm, shm)) << (8 * r);
            wd[2] |= q8(fmaf(f.z, scm, shm)) << (8 * r);
            wd[3] |= q8(fmaf(f.w, scm, shm)) << (8 * r);
        }
        *(int4*)(g_xq + ((size_t)t * 192 + g * 16 + kwl) * 512 + vb) =
            make_int4(wd[0], wd[1], wd[2], wd[3]);
    }
}

// ---------------------------------------------------------------------------
// 2) Fused weight quantization + bias table.
//    blocks [0,288): w_in; [288,384): w_out; [384,448): bias table.
// ---------------------------------------------------------------------------
__global__ void __launch_bounds__(256) quant_wb_kernel(
        const float* __restrict__ w_in,
        const float* __restrict__ w_out,
        const float* __restrict__ emb) {
    const int b = blockIdx.x;
    const int tid = threadIdx.x;
    if (b < 384) {
        const bool is_in = b < 288;
        const float* wsrc = is_in ? w_in : w_out;
        int* wdst = is_in ? g_wq : g_wq2;
        float* sdst = is_in ? g_sb : g_sb2;
        const int width = is_in ? 2304 : 768;
        const int o = (is_in ? b : b - 288) * 8 + (tid >> 5);
        const int lane = tid & 31;
        #pragma unroll
        for (int ch = 0; ch < 12; ch++) {
            float4 wv = *(const float4*)(wsrc + (size_t)o * 768 + ch * 64 + (lane & 15) * 4);
            float m = fmaxf(fmaxf(fabsf(wv.x), fabsf(wv.y)), fmaxf(fabsf(wv.z), fabsf(wv.w)));
            #pragma unroll
            for (int s = 16; s; s >>= 1) m = fmaxf(m, __shfl_xor_sync(0xffffffffu, m, s));
            float sc, invw;
            if (m < 1e-30f) { sc = 0.f; invw = 0.f; }
            else            { sc = m * (1.f / 127.f); invw = 127.f / m; }
            if (lane < 16) {
                int word = (q8(wv.x * invw))
                         | (q8(wv.y * invw) << 8)
                         | (q8(wv.z * invw) << 16)
                         | (q8(wv.w * invw) << 24);
                wdst[(size_t)(ch * 16 + lane) * width + o] = word;
            }
            if (lane == 0) sdst[ch * width + o] = sc;
        }
    } else {
        if (tid >= 64) return;
        const int t = b - 384;
        const int s = tid;
        int rel = t - s;
        int ret = rel < 0 ? 16 : 0;
        int n = rel < 0 ? -rel : rel;
        int bk;
        if (n < 8) {
            bk = n;
        } else {
            float f = logf((float)n / 8.0f);
            f = f / 2.772588722239781f;
            f = f * 8.0f;
            bk = 8 + (int)f;
            if (bk > 15) bk = 15;
        }
        int bucket = ret + bk;
        #pragma unroll
        for (int he = 0; he < 12; he++)
            g_bias[he * 4096 + t * 64 + s] = emb[bucket * 12 + he];
    }
}

// ---------------------------------------------------------------------------
// 3) GEMM1 int8 dp4a (R9 2-stage version): 128v x 128o tile.
// ---------------------------------------------------------------------------
__global__ void __launch_bounds__(256, 2) gemm_qkv_kernel(
        const float* __restrict__ b_in) {
    __shared__ int As[2][16 * 128];
    __shared__ int Bs[2][16 * 128];
    const int tid = threadIdx.x;
    const int tx = tid & 15, ty = tid >> 4;
    const int n0 = blockIdx.y * 128;
    const int o0 = blockIdx.x * 128;
    const int t  = n0 >> 9;
    const int v0 = n0 & 511;
    const int lrow = tid >> 5;
    const int lcol = (tid & 31) * 4;

    float facc[8][8];
    #pragma unroll
    for (int p = 0; p < 8; p++)
        #pragma unroll
        for (int q = 0; q < 8; q++) facc[p][q] = 0.f;

    #pragma unroll
    for (int r = 0; r < 2; r++) {
        int row = lrow + r * 8;
        cp16(&As[0][row * 128 + lcol], g_xq + ((size_t)t * 192 + row) * 512 + v0 + lcol);
        cp16(&Bs[0][row * 128 + lcol], g_wq + (size_t)row * 2304 + o0 + lcol);
    }
    asm volatile("cp.async.commit_group;" ::: "memory");

    for (int ch = 0; ch < 12; ch++) {
        if (ch < 11) {
            const int ns = (ch + 1) & 1;
            const int kw0 = (ch + 1) * 16;
            #pragma unroll
            for (int r = 0; r < 2; r++) {
                int row = lrow + r * 8;
                cp16(&As[ns][row * 128 + lcol],
                     g_xq + ((size_t)t * 192 + kw0 + row) * 512 + v0 + lcol);
                cp16(&Bs[ns][row * 128 + lcol],
                     g_wq + (size_t)(kw0 + row) * 2304 + o0 + lcol);
            }
            asm volatile("cp.async.commit_group;" ::: "memory");
            asm volatile("cp.async.wait_group 1;" ::: "memory");
        } else {
            asm volatile("cp.async.wait_group 0;" ::: "memory");
        }
        __syncthreads();
        const int st = ch & 1;

        const float sa = g_qa[t * 12 + ch];
        float ssb[8];
        #pragma unroll
        for (int g = 0; g < 2; g++)
            #pragma unroll
            for (int j = 0; j < 4; j++)
                ssb[g * 4 + j] = sa * g_sb[ch * 2304 + o0 + tx * 4 + j + 64 * g];

        #pragma unroll
        for (int h = 0; h < 2; h++) {
            int ia[8][4];
            #pragma unroll
            for (int p = 0; p < 8; p++)
                #pragma unroll
                for (int q = 0; q < 4; q++) ia[p][q] = 0;
            #pragma unroll
            for (int kw = 0; kw < 16; kw++) {
                int4 av = *(const int4*)&As[st][kw * 128 + ty * 4 + h * 64];
                int4 b0 = *(const int4*)&Bs[st][kw * 128 + tx * 4];
                int4 b1 = *(const int4*)&Bs[st][kw * 128 + tx * 4 + 64];
                int avv[4] = {av.x, av.y, av.z, av.w};
                int bov[8] = {b0.x, b0.y, b0.z, b0.w, b1.x, b1.y, b1.z, b1.w};
                #pragma unroll
                for (int p = 0; p < 8; p++)
                    #pragma unroll
                    for (int q = 0; q < 4; q++)
                        ia[p][q] = __dp4a(avv[q], bov[p], ia[p][q]);
            }
            #pragma unroll
            for (int p = 0; p < 8; p++)
                #pragma unroll
                for (int q = 0; q < 4; q++)
                    facc[p][h * 4 + q] = fmaf((float)ia[p][q], ssb[p], facc[p][h * 4 + q]);
        }
        __syncthreads();
    }

    float bi[8];
    #pragma unroll
    for (int g = 0; g < 2; g++)
        #pragma unroll
        for (int j = 0; j < 4; j++)
            bi[g * 4 + j] = b_in[o0 + tx * 4 + j + 64 * g];

    #pragma unroll
    for (int g = 0; g < 2; g++) {
        const int ob = o0 + tx * 4 + 64 * g;
        const int he = ob / 192;
        const int jj = ob - he * 192;
        const int part = jj >> 6;
        const int cb = jj & 63;
        float* dst = part == 0 ? g_q : (part == 1 ? g_k : g_v);
        #pragma unroll
        for (int h = 0; h < 2; h++)
            #pragma unroll
            for (int i2 = 0; i2 < 4; i2++) {
                int v = v0 + ty * 4 + i2 + 64 * h;
                float4 w;
                w.x = facc[g * 4 + 0][h * 4 + i2] + bi[g * 4 + 0];
                w.y = facc[g * 4 + 1][h * 4 + i2] + bi[g * 4 + 1];
                w.z = facc[g * 4 + 2][h * 4 + i2] + bi[g * 4 + 2];
                w.w = facc[g * 4 + 3][h * 4 + i2] + bi[g * 4 + 3];
                *(float4*)(dst + (((size_t)v * 12 + he) * 64 + t) * 64 + cb) = w;
            }
    }
}

// ---------------------------------------------------------------------------
// 4) Attention with register-fused q/k LayerNorm; quantized output epilogue.
// ---------------------------------------------------------------------------
__global__ void __launch_bounds__(256) attn_kernel(
        const float* __restrict__ qn_w, const float* __restrict__ qn_b,
        const float* __restrict__ kn_w, const float* __restrict__ kn_b) {
    __shared__ float sqv[64 * 64];
    __shared__ float skp[64 * 65];
    const int tid = threadIdx.x;
    const int blk = blockIdx.x;
    const int he = blk % 12;
    const int v  = blk / 12;
    const float* qb = g_q + (size_t)blk * 4096;
    const float* kb = g_k + (size_t)blk * 4096;
    const int c0 = (tid & 15) * 4;

    const float4 qw4 = *(const float4*)(qn_w + c0);
    const float4 qb4 = *(const float4*)(qn_b + c0);
    const float4 kw4 = *(const float4*)(kn_w + c0);
    const float4 kb4 = *(const float4*)(kn_b + c0);

    #pragma unroll
    for (int it = 0; it < 4; it++) {
        int i = tid * 4 + it * 1024;
        int r = i >> 6;
        float4 qv = *(const float4*)(qb + i);
        {
            float s  = qv.x + qv.y + qv.z + qv.w;
            float s2 = qv.x * qv.x + qv.y * qv.y + qv.z * qv.z + qv.w * qv.w;
            s  += __shfl_xor_sync(0xffffffffu, s, 1);
            s2 += __shfl_xor_sync(0xffffffffu, s2, 1);
            s  += __shfl_xor_sync(0xffffffffu, s, 2);
            s2 += __shfl_xor_sync(0xffffffffu, s2, 2);
            s  += __shfl_xor_sync(0xffffffffu, s, 4);
            s2 += __shfl_xor_sync(0xffffffffu, s2, 4);
            s  += __shfl_xor_sync(0xffffffffu, s, 8);
            s2 += __shfl_xor_sync(0xffffffffu, s2, 8);
            float mu  = s * (1.f / 64.f);
            float var = s2 * (1.f / 64.f) - mu * mu;
            float inv = rsqrtf(var + 1e-5f);
            qv.x = (qv.x - mu) * inv * qw4.x + qb4.x;
            qv.y = (qv.y - mu) * inv * qw4.y + qb4.y;
            qv.z = (qv.z - mu) * inv * qw4.z + qb4.z;
            qv.w = (qv.w - mu) * inv * qw4.w + qb4.w;
        }
        *(float4*)(sqv + i) = qv;
        float4 kv = *(const float4*)(kb + i);
        {
            float s  = kv.x + kv.y + kv.z + kv.w;
            float s2 = kv.x * kv.x + kv.y * kv.y + kv.z * kv.z + kv.w * kv.w;
            s  += __shfl_xor_sync(0xffffffffu, s, 1);
            s2 += __shfl_xor_sync(0xffffffffu, s2, 1);
            s  += __shfl_xor_sync(0xffffffffu, s, 2);
            s2 += __shfl_xor_sync(0xffffffffu, s2, 2);
            s  += __shfl_xor_sync(0xffffffffu, s, 4);
            s2 += __shfl_xor_sync(0xffffffffu, s2, 4);
            s  += __shfl_xor_sync(0xffffffffu, s, 8);
            s2 += __shfl_xor_sync(0xffffffffu, s2, 8);
            float mu  = s * (1.f / 64.f);
            float var = s2 * (1.f / 64.f) - mu * mu;
            float inv = rsqrtf(var + 1e-5f);
            kv.x = (kv.x - mu) * inv * kw4.x + kb4.x;
            kv.y = (kv.y - mu) * inv * kw4.y + kb4.y;
            kv.z = (kv.z - mu) * inv * kw4.z + kb4.z;
            kv.w = (kv.w - mu) * inv * kw4.w + kb4.w;
        }
        float* kd = skp + r * 65 + c0;
        kd[0] = kv.x; kd[1] = kv.y; kd[2] = kv.z; kd[3] = kv.w;
    }
    __syncthreads();

    const int tx = tid & 15, ty = tid >> 4;
    const int t0 = ty * 4, s0 = tx * 4;
    float acc[4][4];
    #pragma unroll
    for (int i = 0; i < 4; i++)
        #pragma unroll
        for (int j = 0; j < 4; j++) acc[i][j] = 0.f;

    #pragma unroll 4
    for (int c = 0; c < 64; c++) {
        float a[4], b[4];
        #pragma unroll
        for (int i = 0; i < 4; i++) a[i] = sqv[(t0 + i) * 64 + c];
        #pragma unroll
        for (int j = 0; j < 4; j++) b[j] = skp[(s0 + j) * 65 + c];
        #pragma unroll
        for (int i = 0; i < 4; i++)
            #pragma unroll
            for (int j = 0; j < 4; j++)
                acc[i][j] = fmaf(a[i], b[j], acc[i][j]);
    }
    __syncthreads();

    const float* bb = g_bias + he * 4096;
    #pragma unroll
    for (int i = 0; i < 4; i++) {
        float4 bi = *(const float4*)(bb + (t0 + i) * 64 + s0);
        float4 pv;
        pv.x = fmaf(acc[i][0], 0.125f, bi.x);
        pv.y = fmaf(acc[i][1], 0.125f, bi.y);
        pv.z = fmaf(acc[i][2], 0.125f, bi.z);
        pv.w = fmaf(acc[i][3], 0.125f, bi.w);
        *(float4*)(skp + (t0 + i) * 64 + s0) = pv;
    }
    __syncthreads();

    const float* vb = g_v + (size_t)blk * 4096;
    #pragma unroll
    for (int it = 0; it < 4; it++) {
        int i = tid * 4 + it * 1024;
        *(float4*)(sqv + i) = *(const float4*)(vb + i);
    }

    {
        int r = tid >> 2, q = tid & 3;
        float* row = skp + r * 64;
        float mx = -1e30f;
        #pragma unroll
        for (int k = 0; k < 16; k++) mx = fmaxf(mx, row[q * 16 + k]);
        mx = fmaxf(mx, __shfl_xor_sync(0xffffffffu, mx, 1));
        mx = fmaxf(mx, __shfl_xor_sync(0xffffffffu, mx, 2));
        float e[16];
        float sum = 0.f;
        #pragma unroll
        for (int k = 0; k < 16; k++) {
            e[k] = expf(row[q * 16 + k] - mx);
            sum += e[k];
        }
        sum += __shfl_xor_sync(0xffffffffu, sum, 1);
        sum += __shfl_xor_sync(0xffffffffu, sum, 2);
        float rs = 1.f / sum;
        #pragma unroll
        for (int k = 0; k < 16; k++) row[q * 16 + k] = e[k] * rs;
    }
    __syncthreads();

    float oacc[4][4];
    #pragma unroll
    for (int i = 0; i < 4; i++)
        #pragma unroll
        for (int j = 0; j < 4; j++) oacc[i][j] = 0.f;

    #pragma unroll 4
    for (int s = 0; s < 64; s++) {
        float4 vv = *(const float4*)(sqv + s * 64 + tx * 4);
        #pragma unroll
        for (int i = 0; i < 4; i++) {
            float p = skp[(t0 + i) * 64 + s];
            oacc[i][0] = fmaf(p, vv.x, oacc[i][0]);
            oacc[i][1] = fmaf(p, vv.y, oacc[i][1]);
            oacc[i][2] = fmaf(p, vv.z, oacc[i][2]);
            oacc[i][3] = fmaf(p, vv.w, oacc[i][3]);
        }
    }

    #pragma unroll
    for (int i = 0; i < 4; i++) {
        float m = fmaxf(fmaxf(fabsf(oacc[i][0]), fabsf(oacc[i][1])),
                        fmaxf(fabsf(oacc[i][2]), fabsf(oacc[i][3])));
        m = fmaxf(m, __shfl_xor_sync(0xffffffffu, m, 1));
        m = fmaxf(m, __shfl_xor_sync(0xffffffffu, m, 2));
        m = fmaxf(m, __shfl_xor_sync(0xffffffffu, m, 4));
        m = fmaxf(m, __shfl_xor_sync(0xffffffffu, m, 8));
        float invs = (m < 1e-30f) ? 0.f : 127.f / m;
        float scl  = (m < 1e-30f) ? 0.f : m * (1.f / 127.f);
        int w = q8(oacc[i][0] * invs)
              | (q8(oacc[i][1] * invs) << 8)
              | (q8(oacc[i][2] * invs) << 16)
              | (q8(oacc[i][3] * invs) << 24);
        int n = (t0 + i) * 512 + v;
        g_oq[(size_t)n * 192 + he * 16 + tx] = w;
        if (tx == 0) g_sa2[(size_t)n * 12 + he] = scl;
    }
}

// ---------------------------------------------------------------------------
// 5) GEMM2 int8 dp4a: out = x + gamma*(o @ w_out^T + b_out)
// ---------------------------------------------------------------------------
__global__ void __launch_bounds__(256, 2) gemm_out_kernel(
        const float* __restrict__ x,
        const float* __restrict__ b_out,
        const float* __restrict__ gamma,
        float* __restrict__ out) {
    __shared__ int As[2][16 * 128];
    __shared__ int Bs[2][16 * 128];
    __shared__ float ssa[12 * 128];
    __shared__ float ssbs[12 * 128];
    const int tid = threadIdx.x;
    const int tx = tid & 15, ty = tid >> 4;
    const int n0 = blockIdx.y * 128;
    const int o0 = blockIdx.x * 128;
    const int t  = n0 >> 9;
    const int v0 = n0 & 511;

    for (int i = tid; i < 1536; i += 256) {
        ssa[i]  = g_sa2[(size_t)(n0 + (i & 127)) * 12 + (i >> 7)];
        ssbs[i] = g_sb2[(i >> 7) * 768 + o0 + (i & 127)];
    }

    const int nl = tid & 127;
    const int half = tid >> 7;
    const int kwl = tid >> 4;
    const int ocl = (tid & 15) * 8;

    float facc[8][8];
    #pragma unroll
    for (int p = 0; p < 8; p++)
        #pragma unroll
        for (int q = 0; q < 8; q++) facc[p][q] = 0.f;

    int4 pa0, pa1, pb0, pb1;
    {
        const int* asrc = g_oq + (size_t)(n0 + nl) * 192 + half * 8;
        pa0 = *(const int4*)(asrc);
        pa1 = *(const int4*)(asrc + 4);
        const int* bsrc = g_wq2 + (size_t)kwl * 768 + o0 + ocl;
        pb0 = *(const int4*)(bsrc);
        pb1 = *(const int4*)(bsrc + 4);
    }
    {
        int base = half * 8;
        As[0][(base + 0) * 128 + nl] = pa0.x;
        As[0][(base + 1) * 128 + nl] = pa0.y;
        As[0][(base + 2) * 128 + nl] = pa0.z;
        As[0][(base + 3) * 128 + nl] = pa0.w;
        As[0][(base + 4) * 128 + nl] = pa1.x;
        As[0][(base + 5) * 128 + nl] = pa1.y;
        As[0][(base + 6) * 128 + nl] = pa1.z;
        As[0][(base + 7) * 128 + nl] = pa1.w;
        *(int4*)&Bs[0][kwl * 128 + ocl]     = pb0;
        *(int4*)&Bs[0][kwl * 128 + ocl + 4] = pb1;
    }
    __syncthreads();

    for (int ch = 0; ch < 12; ch++) {
        const int st = ch & 1;
        if (ch < 11) {
            const int kw0 = (ch + 1) * 16;
            const int* asrc = g_oq + (size_t)(n0 + nl) * 192 + kw0 + half * 8;
            pa0 = *(const int4*)(asrc);
            pa1 = *(const int4*)(asrc + 4);
            const int* bsrc = g_wq2 + (size_t)(kw0 + kwl) * 768 + o0 + ocl;
            pb0 = *(const int4*)(bsrc);
            pb1 = *(const int4*)(bsrc + 4);
        }

        float sbv[8];
        #pragma unroll
        for (int g = 0; g < 2; g++)
            #pragma unroll
            for (int j = 0; j < 4; j++)
                sbv[g * 4 + j] = ssbs[ch * 128 + tx * 4 + j + 64 * g];

        #pragma unroll
        for (int h = 0; h < 2; h++) {
            int ia[8][4];
            #pragma unroll
            for (int p = 0; p < 8; p++)
                #pragma unroll
                for (int q = 0; q < 4; q++) ia[p][q] = 0;
            #pragma unroll
            for (int kw = 0; kw < 16; kw++) {
                int4 av = *(const int4*)&As[st][kw * 128 + ty * 4 + h * 64];
                int4 b0 = *(const int4*)&Bs[st][kw * 128 + tx * 4];
                int4 b1 = *(const int4*)&Bs[st][kw * 128 + tx * 4 + 64];
                int avv[4] = {av.x, av.y, av.z, av.w};
                int bov[8] = {b0.x, b0.y, b0.z, b0.w, b1.x, b1.y, b1.z, b1.w};
                #pragma unroll
                for (int p = 0; p < 8; p++)
                    #pragma unroll
                    for (int q = 0; q < 4; q++)
                        ia[p][q] = __dp4a(avv[q], bov[p], ia[p][q]);
            }
            float sav[4];
            #pragma unroll
            for (int q = 0; q < 4; q++)
                sav[q] = ssa[ch * 128 + ty * 4 + q + 64 * h];
            #pragma unroll
            for (int p = 0; p < 8; p++)
                #pragma unroll
                for (int q = 0; q < 4; q++)
                    facc[p][h * 4 + q] = fmaf((float)ia[p][q], sbv[p] * sav[q],
                                              facc[p][h * 4 + q]);
        }

        if (ch < 11) {
            const int ns = st ^ 1;
            __syncthreads();
            int base = half * 8;
            As[ns][(base + 0) * 128 + nl] = pa0.x;
            As[ns][(base + 1) * 128 + nl] = pa0.y;
            As[ns][(base + 2) * 128 + nl] = pa0.z;
            As[ns][(base + 3) * 128 + nl] = pa0.w;
            As[ns][(base + 4) * 128 + nl] = pa1.x;
            As[ns][(base + 5) * 128 + nl] = pa1.y;
            As[ns][(base + 6) * 128 + nl] = pa1.z;
            As[ns][(base + 7) * 128 + nl] = pa1.w;
            *(int4*)&Bs[ns][kwl * 128 + ocl]     = pb0;
            *(int4*)&Bs[ns][kwl * 128 + ocl + 4] = pb1;
            __syncthreads();
        }
    }

    #pragma unroll
    for (int p = 0; p < 8; p++) {
        const int oc = o0 + tx * 4 + (p & 3) + 64 * (p >> 2);
        const float bo = b_out[oc];
        const float gm = gamma[oc];
        #pragma unroll
        for (int h = 0; h < 2; h++) {
            size_t base = (size_t)t * 393216 + (size_t)oc * 512 + v0 + ty * 4 + 64 * h;
            float4 xv = *(const float4*)(x + base);
            float4 w;
            w.x = xv.x + gm * (facc[p][h * 4 + 0] + bo);
            w.y = xv.y + gm * (facc[p][h * 4 + 1] + bo);
            w.z = xv.z + gm * (facc[p][h * 4 + 2] + bo);
            w.w = xv.w + gm * (facc[p][h * 4 + 3] + bo);
            *(float4*)(out + base) = w;
        }
    }
}

// ---------------------------------------------------------------------------
extern "C" void kernel_launch(void* const* d_in, const int* in_sizes, int n_in,
                              void* d_out, int out_size) {
    const float* x      = (const float*)d_in[0];
    const float* norm1w = (const float*)d_in[1];
    const float* w_in   = (const float*)d_in[2];
    const float* b_in   = (const float*)d_in[3];
    const float* qn_w   = (const float*)d_in[4];
    const float* qn_b   = (const float*)d_in[5];
    const float* kn_w   = (const float*)d_in[6];
    const float* kn_b   = (const float*)d_in[7];
    const float* rel    = (const float*)d_in[8];
    const float* w_out  = (const float*)d_in[9];
    const float* b_out  = (const float*)d_in[10];
    const float* gamma  = (const float*)d_in[11];
    float* out = (float*)d_out;

    gn_stats_quant_kernel<<<768, 256>>>(x, norm1w);            // 0
    quant_wb_kernel<<<448, 256>>>(w_in, w_out, rel);           // 1
    gemm_qkv_kernel<<<dim3(18, 256), 256>>>(b_in);             // 2
    attn_kernel<<<6144, 256>>>(qn_w, qn_b, kn_w, kn_b);        // 3 (profiled)
    gemm_out_kernel<<<dim3(6, 256), 256>>>(x, b_out, gamma, out);  // 4
}

// round 13
// speedup vs baseline: 1.3971x; 1.0151x over previous
#include <cuda_runtime.h>
#include <stdint.h>
#include <math.h>

// Shapes (fixed): T=64, B=1, C=768, V=H*W*D=512, heads=12, hd=64, M=T*V=32768

__device__ float g_qa[64 * 12];
__device__ float g_sb[12 * 2304];
__device__ int   g_xq[64 * 192 * 512];   // x int8 packed: [t][kw][v]
__device__ int   g_wq[192 * 2304];       // w_in int8 packed: [kw][o]
__device__ float g_bias[12 * 64 * 64];
__device__ float g_q[512 * 12 * 64 * 64];
__device__ float g_k[512 * 12 * 64 * 64];
__device__ float g_v[512 * 12 * 64 * 64];
__device__ int   g_oq[32768 * 192];      // attn out int8 packed: [n][kw]
__device__ float g_sa2[32768 * 12];      // attn out scale per (n, head)
__device__ int   g_wq2[192 * 768];       // w_out int8 packed: [kw][oc]
__device__ float g_sb2[12 * 768];        // w_out scale per (chunk, oc)

__device__ __forceinline__ void cp16(void* smem, const void* g) {
    unsigned int s = (unsigned int)__cvta_generic_to_shared(smem);
    asm volatile("cp.async.cg.shared.global [%0], [%1], 16;" :: "r"(s), "l"(g));
}
__device__ __forceinline__ int q8(float f) {
    int q = __float2int_rn(f);
    q = q > 127 ? 127 : q;
    q = q < -127 ? -127 : q;
    return q & 0xFF;
}

// ---------------------------------------------------------------------------
// 1) GroupNorm stats + per-(t,chunk) quant bound + fused x quantization.
// ---------------------------------------------------------------------------
__global__ void gn_stats_quant_kernel(const float* __restrict__ x,
                                      const float* __restrict__ w) {
    const int t = blockIdx.x / 12;
    const int g = blockIdx.x % 12;
    const int tid = threadIdx.x;
    const int cl = tid >> 2;
    const int qq = tid & 3;
    const float* base = x + (size_t)t * 393216 + (size_t)(g * 64 + cl) * 512 + qq * 128;

    float s = 0.f, s2 = 0.f, mx = 0.f;
    #pragma unroll 8
    for (int i = 0; i < 32; i++) {
        float4 a = ((const float4*)base)[i];
        s  += a.x + a.y + a.z + a.w;
        s2 += a.x * a.x + a.y * a.y + a.z * a.z + a.w * a.w;
        mx = fmaxf(mx, fmaxf(fmaxf(fabsf(a.x), fabsf(a.y)), fmaxf(fabsf(a.z), fabsf(a.w))));
    }
    __shared__ float red[256], red2[256], rmax[256];
    __shared__ float sscale[64], sshift[64];
    __shared__ float sqinv;
    red[tid] = s; red2[tid] = s2; rmax[tid] = mx;
    __syncthreads();
    for (int o = 128; o > 0; o >>= 1) {
        if (tid < o) {
            red[tid]  += red[tid + o];
            red2[tid] += red2[tid + o];
        }
        __syncthreads();
    }
    __shared__ float smu, sinv;
    if (tid == 0) {
        float mu  = red[0] * (1.f / 32768.f);
        float var = red2[0] * (1.f / 32768.f) - mu * mu;
        smu  = mu;
        sinv = rsqrtf(var + 1e-5f);
    }
    __syncthreads();
    const float mu = smu, inv = sinv;
    if (tid < 64) {
        float cm = fmaxf(fmaxf(rmax[tid * 4], rmax[tid * 4 + 1]),
                         fmaxf(rmax[tid * 4 + 2], rmax[tid * 4 + 3]));
        int c = g * 64 + tid;
        float sc = inv * w[c];
        sscale[tid] = sc;
        sshift[tid] = -mu * sc;
        red[tid] = fabsf(sc) * (cm + fabsf(mu));
    }
    __syncthreads();
    for (int o = 32; o > 0; o >>= 1) {
        if (tid < o && tid + o < 64) red[tid] = fmaxf(red[tid], red[tid + o]);
        __syncthreads();
    }
    if (tid == 0) {
        float bound = red[0];
        if (bound < 1e-30f) {
            g_qa[t * 12 + g] = 0.f;
            sqinv = 0.f;
        } else {
            g_qa[t * 12 + g] = bound * (1.f / 127.f);
            sqinv = 127.f / bound;
        }
    }
    __syncthreads();

    const float qinv = sqinv;
    const float* xg = x + (size_t)t * 393216 + (size_t)g * 64 * 512;
    for (int i = tid; i < 2048; i += 256) {
        int kwl = i >> 7;
        int vb  = (i & 127) * 4;
        int c0  = kwl * 4;
        int wd[4] = {0, 0, 0, 0};
        #pragma unroll
        for (int r = 0; r < 4; r++) {
            int c = c0 + r;
            float scm = sscale[c] * qinv;
            float shm = sshift[c] * qinv;
            float4 f = *(const float4*)(xg + (size_t)c * 512 + vb);
            wd[0] |= q8(fmaf(f.x, scm, shm)) << (8 * r);
            wd[1] |= q8(fmaf(f.y, scm, shm)) << (8 * r);
            wd[2] |= q8(fmaf(f.z, scm, shm)) << (8 * r);
            wd[3] |= q8(fmaf(f.w, scm, shm)) << (8 * r);
        }
        *(int4*)(g_xq + ((size_t)t * 192 + g * 16 + kwl) * 512 + vb) =
            make_int4(wd[0], wd[1], wd[2], wd[3]);
    }
}

// ---------------------------------------------------------------------------
// 2) Fused weight quantization + bias table.
// ---------------------------------------------------------------------------
__global__ void __launch_bounds__(256) quant_wb_kernel(
        const float* __restrict__ w_in,
        const float* __restrict__ w_out,
        const float* __restrict__ emb) {
    const int b = blockIdx.x;
    const int tid = threadIdx.x;
    if (b < 384) {
        const bool is_in = b < 288;
        const float* wsrc = is_in ? w_in : w_out;
        int* wdst = is_in ? g_wq : g_wq2;
        float* sdst = is_in ? g_sb : g_sb2;
        const int width = is_in ? 2304 : 768;
        const int o = (is_in ? b : b - 288) * 8 + (tid >> 5);
        const int lane = tid & 31;
        #pragma unroll
        for (int ch = 0; ch < 12; ch++) {
            float4 wv = *(const float4*)(wsrc + (size_t)o * 768 + ch * 64 + (lane & 15) * 4);
            float m = fmaxf(fmaxf(fabsf(wv.x), fabsf(wv.y)), fmaxf(fabsf(wv.z), fabsf(wv.w)));
            #pragma unroll
            for (int s = 16; s; s >>= 1) m = fmaxf(m, __shfl_xor_sync(0xffffffffu, m, s));
            float sc, invw;
            if (m < 1e-30f) { sc = 0.f; invw = 0.f; }
            else            { sc = m * (1.f / 127.f); invw = 127.f / m; }
            if (lane < 16) {
                int word = (q8(wv.x * invw))
                         | (q8(wv.y * invw) << 8)
                         | (q8(wv.z * invw) << 16)
                         | (q8(wv.w * invw) << 24);
                wdst[(size_t)(ch * 16 + lane) * width + o] = word;
            }
            if (lane == 0) sdst[ch * width + o] = sc;
        }
    } else {
        if (tid >= 64) return;
        const int t = b - 384;
        const int s = tid;
        int rel = t - s;
        int ret = rel < 0 ? 16 : 0;
        int n = rel < 0 ? -rel : rel;
        int bk;
        if (n < 8) {
            bk = n;
        } else {
            float f = logf((float)n / 8.0f);
            f = f / 2.772588722239781f;
            f = f * 8.0f;
            bk = 8 + (int)f;
            if (bk > 15) bk = 15;
        }
        int bucket = ret + bk;
        #pragma unroll
        for (int he = 0; he < 12; he++)
            g_bias[he * 4096 + t * 64 + s] = emb[bucket * 12 + he];
    }
}

// ---------------------------------------------------------------------------
// 3) GEMM1 int8 dp4a: 128v x 128o tile.
// ---------------------------------------------------------------------------
__global__ void __launch_bounds__(256, 2) gemm_qkv_kernel(
        const float* __restrict__ b_in) {
    __shared__ int As[2][16 * 128];
    __shared__ int Bs[2][16 * 128];
    const int tid = threadIdx.x;
    const int tx = tid & 15, ty = tid >> 4;
    const int n0 = blockIdx.y * 128;
    const int o0 = blockIdx.x * 128;
    const int t  = n0 >> 9;
    const int v0 = n0 & 511;
    const int lrow = tid >> 5;
    const int lcol = (tid & 31) * 4;

    float facc[8][8];
    #pragma unroll
    for (int p = 0; p < 8; p++)
        #pragma unroll
        for (int q = 0; q < 8; q++) facc[p][q] = 0.f;

    #pragma unroll
    for (int r = 0; r < 2; r++) {
        int row = lrow + r * 8;
        cp16(&As[0][row * 128 + lcol], g_xq + ((size_t)t * 192 + row) * 512 + v0 + lcol);
        cp16(&Bs[0][row * 128 + lcol], g_wq + (size_t)row * 2304 + o0 + lcol);
    }
    asm volatile("cp.async.commit_group;" ::: "memory");

    for (int ch = 0; ch < 12; ch++) {
        if (ch < 11) {
            const int ns = (ch + 1) & 1;
            const int kw0 = (ch + 1) * 16;
            #pragma unroll
            for (int r = 0; r < 2; r++) {
                int row = lrow + r * 8;
                cp16(&As[ns][row * 128 + lcol],
                     g_xq + ((size_t)t * 192 + kw0 + row) * 512 + v0 + lcol);
                cp16(&Bs[ns][row * 128 + lcol],
                     g_wq + (size_t)(kw0 + row) * 2304 + o0 + lcol);
            }
            asm volatile("cp.async.commit_group;" ::: "memory");
            asm volatile("cp.async.wait_group 1;" ::: "memory");
        } else {
            asm volatile("cp.async.wait_group 0;" ::: "memory");
        }
        __syncthreads();
        const int st = ch & 1;

        const float sa = g_qa[t * 12 + ch];
        float ssb[8];
        #pragma unroll
        for (int g = 0; g < 2; g++)
            #pragma unroll
            for (int j = 0; j < 4; j++)
                ssb[g * 4 + j] = sa * g_sb[ch * 2304 + o0 + tx * 4 + j + 64 * g];

        #pragma unroll
        for (int h = 0; h < 2; h++) {
            int ia[8][4];
            #pragma unroll
            for (int p = 0; p < 8; p++)
                #pragma unroll
                for (int q = 0; q < 4; q++) ia[p][q] = 0;
            #pragma unroll
            for (int kw = 0; kw < 16; kw++) {
                int4 av = *(const int4*)&As[st][kw * 128 + ty * 4 + h * 64];
                int4 b0 = *(const int4*)&Bs[st][kw * 128 + tx * 4];
                int4 b1 = *(const int4*)&Bs[st][kw * 128 + tx * 4 + 64];
                int avv[4] = {av.x, av.y, av.z, av.w};
                int bov[8] = {b0.x, b0.y, b0.z, b0.w, b1.x, b1.y, b1.z, b1.w};
                #pragma unroll
                for (int p = 0; p < 8; p++)
                    #pragma unroll
                    for (int q = 0; q < 4; q++)
                        ia[p][q] = __dp4a(avv[q], bov[p], ia[p][q]);
            }
            #pragma unroll
            for (int p = 0; p < 8; p++)
                #pragma unroll
                for (int q = 0; q < 4; q++)
                    facc[p][h * 4 + q] = fmaf((float)ia[p][q], ssb[p], facc[p][h * 4 + q]);
        }
        __syncthreads();
    }

    float bi[8];
    #pragma unroll
    for (int g = 0; g < 2; g++)
        #pragma unroll
        for (int j = 0; j < 4; j++)
            bi[g * 4 + j] = b_in[o0 + tx * 4 + j + 64 * g];

    #pragma unroll
    for (int g = 0; g < 2; g++) {
        const int ob = o0 + tx * 4 + 64 * g;
        const int he = ob / 192;
        const int jj = ob - he * 192;
        const int part = jj >> 6;
        const int cb = jj & 63;
        float* dst = part == 0 ? g_q : (part == 1 ? g_k : g_v);
        #pragma unroll
        for (int h = 0; h < 2; h++)
            #pragma unroll
            for (int i2 = 0; i2 < 4; i2++) {
                int v = v0 + ty * 4 + i2 + 64 * h;
                float4 w;
                w.x = facc[g * 4 + 0][h * 4 + i2] + bi[g * 4 + 0];
                w.y = facc[g * 4 + 1][h * 4 + i2] + bi[g * 4 + 1];
                w.z = facc[g * 4 + 2][h * 4 + i2] + bi[g * 4 + 2];
                w.w = facc[g * 4 + 3][h * 4 + i2] + bi[g * 4 + 3];
                *(float4*)(dst + (((size_t)v * 12 + he) * 64 + t) * 64 + cb) = w;
            }
    }
}

// ---------------------------------------------------------------------------
// 4) Attention: fused q/k LayerNorm + int8 dp4a QK^T; fp32 softmax+PV;
//    quantized output epilogue.
// ---------------------------------------------------------------------------
__global__ void __launch_bounds__(256) attn_kernel(
        const float* __restrict__ qn_w, const float* __restrict__ qn_b,
        const float* __restrict__ kn_w, const float* __restrict__ kn_b) {
    __shared__ int   sqi[64 * 16];       // q int8 packed [row][word]
    __shared__ int   ski[64 * 17];       // k int8 packed, pitch 17
    __shared__ float sqs[64], sks[64];   // per-row dequant scales (max/127)
    __shared__ float sp[64 * 64];        // scores / P
    __shared__ float sv[64 * 64];        // V
    const int tid = threadIdx.x;
    const int blk = blockIdx.x;
    const int he = blk % 12;
    const int v  = blk / 12;
    const float* qb = g_q + (size_t)blk * 4096;
    const float* kb = g_k + (size_t)blk * 4096;
    const float* vb = g_v + (size_t)blk * 4096;
    const int c0 = (tid & 15) * 4;
    const int wi = tid & 15;             // word index this lane owns

    // kick off V loads (consumed after softmax)
    #pragma unroll
    for (int it = 0; it < 4; it++) {
        int i = tid * 4 + it * 1024;
        cp16(&sv[i], vb + i);
    }
    asm volatile("cp.async.commit_group;" ::: "memory");

    const float4 qw4 = *(const float4*)(qn_w + c0);
    const float4 qb4 = *(const float4*)(qn_b + c0);
    const float4 kw4 = *(const float4*)(kn_w + c0);
    const float4 kb4 = *(const float4*)(kn_b + c0);

    #pragma unroll
    for (int it = 0; it < 4; it++) {
        int i = tid * 4 + it * 1024;
        int r = i >> 6;
        // ---- q: load, LN, quantize, pack ----
        float4 qv = *(const float4*)(qb + i);
        {
            float s  = qv.x + qv.y + qv.z + qv.w;
            float s2 = qv.x * qv.x + qv.y * qv.y + qv.z * qv.z + qv.w * qv.w;
            s  += __shfl_xor_sync(0xffffffffu, s, 1);
            s2 += __shfl_xor_sync(0xffffffffu, s2, 1);
            s  += __shfl_xor_sync(0xffffffffu, s, 2);
            s2 += __shfl_xor_sync(0xffffffffu, s2, 2);
            s  += __shfl_xor_sync(0xffffffffu, s, 4);
            s2 += __shfl_xor_sync(0xffffffffu, s2, 4);
            s  += __shfl_xor_sync(0xffffffffu, s, 8);
            s2 += __shfl_xor_sync(0xffffffffu, s2, 8);
            float mu  = s * (1.f / 64.f);
            float var = s2 * (1.f / 64.f) - mu * mu;
            float inv = rsqrtf(var + 1e-5f);
            qv.x = (qv.x - mu) * inv * qw4.x + qb4.x;
            qv.y = (qv.y - mu) * inv * qw4.y + qb4.y;
            qv.z = (qv.z - mu) * inv * qw4.z + qb4.z;
            qv.w = (qv.w - mu) * inv * qw4.w + qb4.w;
            float m = fmaxf(fmaxf(fabsf(qv.x), fabsf(qv.y)),
                            fmaxf(fabsf(qv.z), fabsf(qv.w)));
            m = fmaxf(m, __shfl_xor_sync(0xffffffffu, m, 1));
            m = fmaxf(m, __shfl_xor_sync(0xffffffffu, m, 2));
            m = fmaxf(m, __shfl_xor_sync(0xffffffffu, m, 4));
            m = fmaxf(m, __shfl_xor_sync(0xffffffffu, m, 8));
            float invs = (m < 1e-30f) ? 0.f : 127.f / m;
            int word = q8(qv.x * invs)
                     | (q8(qv.y * invs) << 8)
                     | (q8(qv.z * invs) << 16)
                     | (q8(qv.w * invs) << 24);
            sqi[r * 16 + wi] = word;
            if (wi == 0) sqs[r] = (m < 1e-30f) ? 0.f : m * (1.f / 127.f);
        }
        // ---- k: load, LN, quantize, pack ----
        float4 kv = *(const float4*)(kb + i);
        {
            float s  = kv.x + kv.y + kv.z + kv.w;
            float s2 = kv.x * kv.x + kv.y * kv.y + kv.z * kv.z + kv.w * kv.w;
            s  += __shfl_xor_sync(0xffffffffu, s, 1);
            s2 += __shfl_xor_sync(0xffffffffu, s2, 1);
            s  += __shfl_xor_sync(0xffffffffu, s, 2);
            s2 += __shfl_xor_sync(0xffffffffu, s2, 2);
            s  += __shfl_xor_sync(0xffffffffu, s, 4);
            s2 += __shfl_xor_sync(0xffffffffu, s2, 4);
            s  += __shfl_xor_sync(0xffffffffu, s, 8);
            s2 += __shfl_xor_sync(0xffffffffu, s2, 8);
            float mu  = s * (1.f / 64.f);
            float var = s2 * (1.f / 64.f) - mu * mu;
            float inv = rsqrtf(var + 1e-5f);
            kv.x = (kv.x - mu) * inv * kw4.x + kb4.x;
            kv.y = (kv.y - mu) * inv * kw4.y + kb4.y;
            kv.z = (kv.z - mu) * inv * kw4.z + kb4.z;
            kv.w = (kv.w - mu) * inv * kw4.w + kb4.w;
            float m = fmaxf(fmaxf(fabsf(kv.x), fabsf(kv.y)),
                            fmaxf(fabsf(kv.z), fabsf(kv.w)));
            m = fmaxf(m, __shfl_xor_sync(0xffffffffu, m, 1));
            m = fmaxf(m, __shfl_xor_sync(0xffffffffu, m, 2));
            m = fmaxf(m, __shfl_xor_sync(0xffffffffu, m, 4));
            m = fmaxf(m, __shfl_xor_sync(0xffffffffu, m, 8));
            float invs = (m < 1e-30f) ? 0.f : 127.f / m;
            int word = q8(kv.x * invs)
                     | (q8(kv.y * invs) << 8)
                     | (q8(kv.z * invs) << 16)
                     | (q8(kv.w * invs) << 24);
            ski[r * 17 + wi] = word;
            if (wi == 0) sks[r] = (m < 1e-30f) ? 0.f : m * (1.f / 127.f);
        }
    }
    __syncthreads();

    const int tx = tid & 15, ty = tid >> 4;
    const int t0 = ty * 4, s0 = tx * 4;

    // QK^T via dp4a
    int iacc[4][4];
    #pragma unroll
    for (int i = 0; i < 4; i++)
        #pragma unroll
        for (int j = 0; j < 4; j++) iacc[i][j] = 0;

    #pragma unroll
    for (int w = 0; w < 16; w++) {
        int a_[4], b_[4];
        #pragma unroll
        for (int i = 0; i < 4; i++) a_[i] = sqi[(t0 + i) * 16 + w];
        #pragma unroll
        for (int j = 0; j < 4; j++) b_[j] = ski[(s0 + j) * 17 + w];
        #pragma unroll
        for (int i = 0; i < 4; i++)
            #pragma unroll
            for (int j = 0; j < 4; j++)
                iacc[i][j] = __dp4a(a_[i], b_[j], iacc[i][j]);
    }

    float qsc[4], ksc[4];
    #pragma unroll
    for (int i = 0; i < 4; i++) qsc[i] = sqs[t0 + i] * 0.125f;
    #pragma unroll
    for (int j = 0; j < 4; j++) ksc[j] = sks[s0 + j];

    const float* bb = g_bias + he * 4096;
    #pragma unroll
    for (int i = 0; i < 4; i++) {
        float4 bi = *(const float4*)(bb + (t0 + i) * 64 + s0);
        float4 pv;
        pv.x = fmaf((float)iacc[i][0], qsc[i] * ksc[0], bi.x);
        pv.y = fmaf((float)iacc[i][1], qsc[i] * ksc[1], bi.y);
        pv.z = fmaf((float)iacc[i][2], qsc[i] * ksc[2], bi.z);
        pv.w = fmaf((float)iacc[i][3], qsc[i] * ksc[3], bi.w);
        *(float4*)(sp + (t0 + i) * 64 + s0) = pv;
    }
    __syncthreads();

    // softmax (4 threads per row)
    {
        int r = tid >> 2, q = tid & 3;
        float* row = sp + r * 64;
        float mx = -1e30f;
        #pragma unroll
        for (int k = 0; k < 16; k++) mx = fmaxf(mx, row[q * 16 + k]);
        mx = fmaxf(mx, __shfl_xor_sync(0xffffffffu, mx, 1));
        mx = fmaxf(mx, __shfl_xor_sync(0xffffffffu, mx, 2));
        float e[16];
        float sum = 0.f;
        #pragma unroll
        for (int k = 0; k < 16; k++) {
            e[k] = expf(row[q * 16 + k] - mx);
            sum += e[k];
        }
        sum += __shfl_xor_sync(0xffffffffu, sum, 1);
        sum += __shfl_xor_sync(0xffffffffu, sum, 2);
        float rs = 1.f / sum;
        #pragma unroll
        for (int k = 0; k < 16; k++) row[q * 16 + k] = e[k] * rs;
    }
    asm volatile("cp.async.wait_group 0;" ::: "memory");
    __syncthreads();

    // O = P @ V
    float oacc[4][4];
    #pragma unroll
    for (int i = 0; i < 4; i++)
        #pragma unroll
        for (int j = 0; j < 4; j++) oacc[i][j] = 0.f;

    #pragma unroll 4
    for (int s = 0; s < 64; s++) {
        float4 vv = *(const float4*)(sv + s * 64 + tx * 4);
        #pragma unroll
        for (int i = 0; i < 4; i++) {
            float p = sp[(t0 + i) * 64 + s];
            oacc[i][0] = fmaf(p, vv.x, oacc[i][0]);
            oacc[i][1] = fmaf(p, vv.y, oacc[i][1]);
            oacc[i][2] = fmaf(p, vv.z, oacc[i][2]);
            oacc[i][3] = fmaf(p, vv.w, oacc[i][3]);
        }
    }

    // quantize per (n, head) row for GEMM2
    #pragma unroll
    for (int i = 0; i < 4; i++) {
        float m = fmaxf(fmaxf(fabsf(oacc[i][0]), fabsf(oacc[i][1])),
                        fmaxf(fabsf(oacc[i][2]), fabsf(oacc[i][3])));
        m = fmaxf(m, __shfl_xor_sync(0xffffffffu, m, 1));
        m = fmaxf(m, __shfl_xor_sync(0xffffffffu, m, 2));
        m = fmaxf(m, __shfl_xor_sync(0xffffffffu, m, 4));
        m = fmaxf(m, __shfl_xor_sync(0xffffffffu, m, 8));
        float invs = (m < 1e-30f) ? 0.f : 127.f / m;
        float scl  = (m < 1e-30f) ? 0.f : m * (1.f / 127.f);
        int w = q8(oacc[i][0] * invs)
              | (q8(oacc[i][1] * invs) << 8)
              | (q8(oacc[i][2] * invs) << 16)
              | (q8(oacc[i][3] * invs) << 24);
        int n = (t0 + i) * 512 + v;
        g_oq[(size_t)n * 192 + he * 16 + tx] = w;
        if (tx == 0) g_sa2[(size_t)n * 12 + he] = scl;
    }
}

// ---------------------------------------------------------------------------
// 5) GEMM2 int8 dp4a: out = x + gamma*(o @ w_out^T + b_out)
// ---------------------------------------------------------------------------
__global__ void __launch_bounds__(256, 2) gemm_out_kernel(
        const float* __restrict__ x,
        const float* __restrict__ b_out,
        const float* __restrict__ gamma,
        float* __restrict__ out) {
    __shared__ int As[2][16 * 128];
    __shared__ int Bs[2][16 * 128];
    __shared__ float ssa[12 * 128];
    __shared__ float ssbs[12 * 128];
    const int tid = threadIdx.x;
    const int tx = tid & 15, ty = tid >> 4;
    const int n0 = blockIdx.y * 128;
    const int o0 = blockIdx.x * 128;
    const int t  = n0 >> 9;
    const int v0 = n0 & 511;

    for (int i = tid; i < 1536; i += 256) {
        ssa[i]  = g_sa2[(size_t)(n0 + (i & 127)) * 12 + (i >> 7)];
        ssbs[i] = g_sb2[(i >> 7) * 768 + o0 + (i & 127)];
    }

    const int nl = tid & 127;
    const int half = tid >> 7;
    const int kwl = tid >> 4;
    const int ocl = (tid & 15) * 8;

    float facc[8][8];
    #pragma unroll
    for (int p = 0; p < 8; p++)
        #pragma unroll
        for (int q = 0; q < 8; q++) facc[p][q] = 0.f;

    int4 pa0, pa1, pb0, pb1;
    {
        const int* asrc = g_oq + (size_t)(n0 + nl) * 192 + half * 8;
        pa0 = *(const int4*)(asrc);
        pa1 = *(const int4*)(asrc + 4);
        const int* bsrc = g_wq2 + (size_t)kwl * 768 + o0 + ocl;
        pb0 = *(const int4*)(bsrc);
        pb1 = *(const int4*)(bsrc + 4);
    }
    {
        int base = half * 8;
        As[0][(base + 0) * 128 + nl] = pa0.x;
        As[0][(base + 1) * 128 + nl] = pa0.y;
        As[0][(base + 2) * 128 + nl] = pa0.z;
        As[0][(base + 3) * 128 + nl] = pa0.w;
        As[0][(base + 4) * 128 + nl] = pa1.x;
        As[0][(base + 5) * 128 + nl] = pa1.y;
        As[0][(base + 6) * 128 + nl] = pa1.z;
        As[0][(base + 7) * 128 + nl] = pa1.w;
        *(int4*)&Bs[0][kwl * 128 + ocl]     = pb0;
        *(int4*)&Bs[0][kwl * 128 + ocl + 4] = pb1;
    }
    __syncthreads();

    for (int ch = 0; ch < 12; ch++) {
        const int st = ch & 1;
        if (ch < 11) {
            const int kw0 = (ch + 1) * 16;
            const int* asrc = g_oq + (size_t)(n0 + nl) * 192 + kw0 + half * 8;
            pa0 = *(const int4*)(asrc);
            pa1 = *(const int4*)(asrc + 4);
            const int* bsrc = g_wq2 + (size_t)(kw0 + kwl) * 768 + o0 + ocl;
            pb0 = *(const int4*)(bsrc);
            pb1 = *(const int4*)(bsrc + 4);
        }

        float sbv[8];
        #pragma unroll
        for (int g = 0; g < 2; g++)
            #pragma unroll
            for (int j = 0; j < 4; j++)
                sbv[g * 4 + j] = ssbs[ch * 128 + tx * 4 + j + 64 * g];

        #pragma unroll
        for (int h = 0; h < 2; h++) {
            int ia[8][4];
            #pragma unroll
            for (int p = 0; p < 8; p++)
                #pragma unroll
                for (int q = 0; q < 4; q++) ia[p][q] = 0;
            #pragma unroll
            for (int kw = 0; kw < 16; kw++) {
                int4 av = *(const int4*)&As[st][kw * 128 + ty * 4 + h * 64];
                int4 b0 = *(const int4*)&Bs[st][kw * 128 + tx * 4];
                int4 b1 = *(const int4*)&Bs[st][kw * 128 + tx * 4 + 64];
                int avv[4] = {av.x, av.y, av.z, av.w};
                int bov[8] = {b0.x, b0.y, b0.z, b0.w, b1.x, b1.y, b1.z, b1.w};
                #pragma unroll
                for (int p = 0; p < 8; p++)
                    #pragma unroll
                    for (int q = 0; q < 4; q++)
                        ia[p][q] = __dp4a(avv[q], bov[p], ia[p][q]);
            }
            float sav[4];
            #pragma unroll
            for (int q = 0; q < 4; q++)
                sav[q] = ssa[ch * 128 + ty * 4 + q + 64 * h];
            #pragma unroll
            for (int p = 0; p < 8; p++)
                #pragma unroll
                for (int q = 0; q < 4; q++)
                    facc[p][h * 4 + q] = fmaf((float)ia[p][q], sbv[p] * sav[q],
                                              facc[p][h * 4 + q]);
        }

        if (ch < 11) {
            const int ns = st ^ 1;
            __syncthreads();
            int base = half * 8;
            As[ns][(base + 0) * 128 + nl] = pa0.x;
            As[ns][(base + 1) * 128 + nl] = pa0.y;
            As[ns][(base + 2) * 128 + nl] = pa0.z;
            As[ns][(base + 3) * 128 + nl] = pa0.w;
            As[ns][(base + 4) * 128 + nl] = pa1.x;
            As[ns][(base + 5) * 128 + nl] = pa1.y;
            As[ns][(base + 6) * 128 + nl] = pa1.z;
            As[ns][(base + 7) * 128 + nl] = pa1.w;
            *(int4*)&Bs[ns][kwl * 128 + ocl]     = pb0;
            *(int4*)&Bs[ns][kwl * 128 + ocl + 4] = pb1;
            __syncthreads();
        }
    }

    #pragma unroll
    for (int p = 0; p < 8; p++) {
        const int oc = o0 + tx * 4 + (p & 3) + 64 * (p >> 2);
        const float bo = b_out[oc];
        const float gm = gamma[oc];
        #pragma unroll
        for (int h = 0; h < 2; h++) {
            size_t base = (size_t)t * 393216 + (size_t)oc * 512 + v0 + ty * 4 + 64 * h;
            float4 xv = *(const float4*)(x + base);
            float4 w;
            w.x = xv.x + gm * (facc[p][h * 4 + 0] + bo);
            w.y = xv.y + gm * (facc[p][h * 4 + 1] + bo);
            w.z = xv.z + gm * (facc[p][h * 4 + 2] + bo);
            w.w = xv.w + gm * (facc[p][h * 4 + 3] + bo);
            *(float4*)(out + base) = w;
        }
    }
}

// ---------------------------------------------------------------------------
extern "C" void kernel_launch(void* const* d_in, const int* in_sizes, int n_in,
                              void* d_out, int out_size) {
    const float* x      = (const float*)d_in[0];
    const float* norm1w = (const float*)d_in[1];
    const float* w_in   = (const float*)d_in[2];
    const float* b_in   = (const float*)d_in[3];
    const float* qn_w   = (const float*)d_in[4];
    const float* qn_b   = (const float*)d_in[5];
    const float* kn_w   = (const float*)d_in[6];
    const float* kn_b   = (const float*)d_in[7];
    const float* rel    = (const float*)d_in[8];
    const float* w_out  = (const float*)d_in[9];
    const float* b_out  = (const float*)d_in[10];
    const float* gamma  = (const float*)d_in[11];
    float* out = (float*)d_out;

    gn_stats_quant_kernel<<<768, 256>>>(x, norm1w);            // 0
    quant_wb_kernel<<<448, 256>>>(w_in, w_out, rel);           // 1
    gemm_qkv_kernel<<<dim3(18, 256), 256>>>(b_in);             // 2
    attn_kernel<<<6144, 256>>>(qn_w, qn_b, kn_w, kn_b);        // 3 (profiled)
    gemm_out_kernel<<<dim3(6, 256), 256>>>(x, b_out, gamma, out);  // 4
}

// round 14
// speedup vs baseline: 1.4135x; 1.0117x over previous
#include <cuda_runtime.h>
#include <stdint.h>
#include <math.h>

// Shapes (fixed): T=64, B=1, C=768, V=H*W*D=512, heads=12, hd=64, M=T*V=32768

__device__ float g_qa[64 * 12];
__device__ float g_sb[12 * 2304];
__device__ int   g_xq[64 * 192 * 512];   // x int8 packed: [t][kw][v]
__device__ int   g_wq[192 * 2304];       // w_in int8 packed: [kw][o]
__device__ float g_bias[12 * 64 * 64];
__device__ float g_q[512 * 12 * 64 * 64];
__device__ float g_k[512 * 12 * 64 * 64];
__device__ float g_v[512 * 12 * 64 * 64];
__device__ int   g_oq[32768 * 192];      // attn out int8 packed: [n][kw]
__device__ float g_sa2[32768 * 12];      // attn out scale per (n, head)
__device__ int   g_wq2[192 * 768];       // w_out int8 packed: [kw][oc]
__device__ float g_sb2[12 * 768];        // w_out scale per (chunk, oc)

__device__ __forceinline__ void cp16(void* smem, const void* g) {
    unsigned int s = (unsigned int)__cvta_generic_to_shared(smem);
    asm volatile("cp.async.cg.shared.global [%0], [%1], 16;" :: "r"(s), "l"(g));
}
__device__ __forceinline__ int q8(float f) {
    int q = __float2int_rn(f);
    q = q > 127 ? 127 : q;
    q = q < -127 ? -127 : q;
    return q & 0xFF;
}

// ---------------------------------------------------------------------------
// 1) GroupNorm stats + per-(t,chunk) quant bound + fused x quantization.
// ---------------------------------------------------------------------------
__global__ void gn_stats_quant_kernel(const float* __restrict__ x,
                                      const float* __restrict__ w) {
    const int t = blockIdx.x / 12;
    const int g = blockIdx.x % 12;
    const int tid = threadIdx.x;
    const int cl = tid >> 2;
    const int qq = tid & 3;
    const float* base = x + (size_t)t * 393216 + (size_t)(g * 64 + cl) * 512 + qq * 128;

    float s = 0.f, s2 = 0.f, mx = 0.f;
    #pragma unroll 8
    for (int i = 0; i < 32; i++) {
        float4 a = ((const float4*)base)[i];
        s  += a.x + a.y + a.z + a.w;
        s2 += a.x * a.x + a.y * a.y + a.z * a.z + a.w * a.w;
        mx = fmaxf(mx, fmaxf(fmaxf(fabsf(a.x), fabsf(a.y)), fmaxf(fabsf(a.z), fabsf(a.w))));
    }
    __shared__ float red[256], red2[256], rmax[256];
    __shared__ float sscale[64], sshift[64];
    __shared__ float sqinv;
    red[tid] = s; red2[tid] = s2; rmax[tid] = mx;
    __syncthreads();
    for (int o = 128; o > 0; o >>= 1) {
        if (tid < o) {
            red[tid]  += red[tid + o];
            red2[tid] += red2[tid + o];
        }
        __syncthreads();
    }
    __shared__ float smu, sinv;
    if (tid == 0) {
        float mu  = red[0] * (1.f / 32768.f);
        float var = red2[0] * (1.f / 32768.f) - mu * mu;
        smu  = mu;
        sinv = rsqrtf(var + 1e-5f);
    }
    __syncthreads();
    const float mu = smu, inv = sinv;
    if (tid < 64) {
        float cm = fmaxf(fmaxf(rmax[tid * 4], rmax[tid * 4 + 1]),
                         fmaxf(rmax[tid * 4 + 2], rmax[tid * 4 + 3]));
        int c = g * 64 + tid;
        float sc = inv * w[c];
        sscale[tid] = sc;
        sshift[tid] = -mu * sc;
        red[tid] = fabsf(sc) * (cm + fabsf(mu));
    }
    __syncthreads();
    for (int o = 32; o > 0; o >>= 1) {
        if (tid < o && tid + o < 64) red[tid] = fmaxf(red[tid], red[tid + o]);
        __syncthreads();
    }
    if (tid == 0) {
        float bound = red[0];
        if (bound < 1e-30f) {
            g_qa[t * 12 + g] = 0.f;
            sqinv = 0.f;
        } else {
            g_qa[t * 12 + g] = bound * (1.f / 127.f);
            sqinv = 127.f / bound;
        }
    }
    __syncthreads();

    const float qinv = sqinv;
    const float* xg = x + (size_t)t * 393216 + (size_t)g * 64 * 512;
    for (int i = tid; i < 2048; i += 256) {
        int kwl = i >> 7;
        int vb  = (i & 127) * 4;
        int c0  = kwl * 4;
        int wd[4] = {0, 0, 0, 0};
        #pragma unroll
        for (int r = 0; r < 4; r++) {
            int c = c0 + r;
            float scm = sscale[c] * qinv;
            float shm = sshift[c] * qinv;
            float4 f = *(const float4*)(xg + (size_t)c * 512 + vb);
            wd[0] |= q8(fmaf(f.x, scm, shm)) << (8 * r);
            wd[1] |= q8(fmaf(f.y, scm, shm)) << (8 * r);
            wd[2] |= q8(fmaf(f.z, scm, shm)) << (8 * r);
            wd[3] |= q8(fmaf(f.w, scm, shm)) << (8 * r);
        }
        *(int4*)(g_xq + ((size_t)t * 192 + g * 16 + kwl) * 512 + vb) =
            make_int4(wd[0], wd[1], wd[2], wd[3]);
    }
}

// ---------------------------------------------------------------------------
// 2) Fused weight quantization + bias table.
// ---------------------------------------------------------------------------
__global__ void __launch_bounds__(256) quant_wb_kernel(
        const float* __restrict__ w_in,
        const float* __restrict__ w_out,
        const float* __restrict__ emb) {
    const int b = blockIdx.x;
    const int tid = threadIdx.x;
    if (b < 384) {
        const bool is_in = b < 288;
        const float* wsrc = is_in ? w_in : w_out;
        int* wdst = is_in ? g_wq : g_wq2;
        float* sdst = is_in ? g_sb : g_sb2;
        const int width = is_in ? 2304 : 768;
        const int o = (is_in ? b : b - 288) * 8 + (tid >> 5);
        const int lane = tid & 31;
        #pragma unroll
        for (int ch = 0; ch < 12; ch++) {
            float4 wv = *(const float4*)(wsrc + (size_t)o * 768 + ch * 64 + (lane & 15) * 4);
            float m = fmaxf(fmaxf(fabsf(wv.x), fabsf(wv.y)), fmaxf(fabsf(wv.z), fabsf(wv.w)));
            #pragma unroll
            for (int s = 16; s; s >>= 1) m = fmaxf(m, __shfl_xor_sync(0xffffffffu, m, s));
            float sc, invw;
            if (m < 1e-30f) { sc = 0.f; invw = 0.f; }
            else            { sc = m * (1.f / 127.f); invw = 127.f / m; }
            if (lane < 16) {
                int word = (q8(wv.x * invw))
                         | (q8(wv.y * invw) << 8)
                         | (q8(wv.z * invw) << 16)
                         | (q8(wv.w * invw) << 24);
                wdst[(size_t)(ch * 16 + lane) * width + o] = word;
            }
            if (lane == 0) sdst[ch * width + o] = sc;
        }
    } else {
        if (tid >= 64) return;
        const int t = b - 384;
        const int s = tid;
        int rel = t - s;
        int ret = rel < 0 ? 16 : 0;
        int n = rel < 0 ? -rel : rel;
        int bk;
        if (n < 8) {
            bk = n;
        } else {
            float f = logf((float)n / 8.0f);
            f = f / 2.772588722239781f;
            f = f * 8.0f;
            bk = 8 + (int)f;
            if (bk > 15) bk = 15;
        }
        int bucket = ret + bk;
        #pragma unroll
        for (int he = 0; he < 12; he++)
            g_bias[he * 4096 + t * 64 + s] = emb[bucket * 12 + he];
    }
}

// ---------------------------------------------------------------------------
// 3) GEMM1 int8 dp4a: 128v x 128o tile.
// ---------------------------------------------------------------------------
__global__ void __launch_bounds__(256, 2) gemm_qkv_kernel(
        const float* __restrict__ b_in) {
    __shared__ int As[2][16 * 128];
    __shared__ int Bs[2][16 * 128];
    const int tid = threadIdx.x;
    const int tx = tid & 15, ty = tid >> 4;
    const int n0 = blockIdx.y * 128;
    const int o0 = blockIdx.x * 128;
    const int t  = n0 >> 9;
    const int v0 = n0 & 511;
    const int lrow = tid >> 5;
    const int lcol = (tid & 31) * 4;

    float facc[8][8];
    #pragma unroll
    for (int p = 0; p < 8; p++)
        #pragma unroll
        for (int q = 0; q < 8; q++) facc[p][q] = 0.f;

    #pragma unroll
    for (int r = 0; r < 2; r++) {
        int row = lrow + r * 8;
        cp16(&As[0][row * 128 + lcol], g_xq + ((size_t)t * 192 + row) * 512 + v0 + lcol);
        cp16(&Bs[0][row * 128 + lcol], g_wq + (size_t)row * 2304 + o0 + lcol);
    }
    asm volatile("cp.async.commit_group;" ::: "memory");

    for (int ch = 0; ch < 12; ch++) {
        if (ch < 11) {
            const int ns = (ch + 1) & 1;
            const int kw0 = (ch + 1) * 16;
            #pragma unroll
            for (int r = 0; r < 2; r++) {
                int row = lrow + r * 8;
                cp16(&As[ns][row * 128 + lcol],
                     g_xq + ((size_t)t * 192 + kw0 + row) * 512 + v0 + lcol);
                cp16(&Bs[ns][row * 128 + lcol],
                     g_wq + (size_t)(kw0 + row) * 2304 + o0 + lcol);
            }
            asm volatile("cp.async.commit_group;" ::: "memory");
            asm volatile("cp.async.wait_group 1;" ::: "memory");
        } else {
            asm volatile("cp.async.wait_group 0;" ::: "memory");
        }
        __syncthreads();
        const int st = ch & 1;

        const float sa = g_qa[t * 12 + ch];
        float ssb[8];
        #pragma unroll
        for (int g = 0; g < 2; g++)
            #pragma unroll
            for (int j = 0; j < 4; j++)
                ssb[g * 4 + j] = sa * g_sb[ch * 2304 + o0 + tx * 4 + j + 64 * g];

        #pragma unroll
        for (int h = 0; h < 2; h++) {
            int ia[8][4];
            #pragma unroll
            for (int p = 0; p < 8; p++)
                #pragma unroll
                for (int q = 0; q < 4; q++) ia[p][q] = 0;
            #pragma unroll
            for (int kw = 0; kw < 16; kw++) {
                int4 av = *(const int4*)&As[st][kw * 128 + ty * 4 + h * 64];
                int4 b0 = *(const int4*)&Bs[st][kw * 128 + tx * 4];
                int4 b1 = *(const int4*)&Bs[st][kw * 128 + tx * 4 + 64];
                int avv[4] = {av.x, av.y, av.z, av.w};
                int bov[8] = {b0.x, b0.y, b0.z, b0.w, b1.x, b1.y, b1.z, b1.w};
                #pragma unroll
                for (int p = 0; p < 8; p++)
                    #pragma unroll
                    for (int q = 0; q < 4; q++)
                        ia[p][q] = __dp4a(avv[q], bov[p], ia[p][q]);
            }
            #pragma unroll
            for (int p = 0; p < 8; p++)
                #pragma unroll
                for (int q = 0; q < 4; q++)
                    facc[p][h * 4 + q] = fmaf((float)ia[p][q], ssb[p], facc[p][h * 4 + q]);
        }
        __syncthreads();
    }

    float bi[8];
    #pragma unroll
    for (int g = 0; g < 2; g++)
        #pragma unroll
        for (int j = 0; j < 4; j++)
            bi[g * 4 + j] = b_in[o0 + tx * 4 + j + 64 * g];

    #pragma unroll
    for (int g = 0; g < 2; g++) {
        const int ob = o0 + tx * 4 + 64 * g;
        const int he = ob / 192;
        const int jj = ob - he * 192;
        const int part = jj >> 6;
        const int cb = jj & 63;
        float* dst = part == 0 ? g_q : (part == 1 ? g_k : g_v);
        #pragma unroll
        for (int h = 0; h < 2; h++)
            #pragma unroll
            for (int i2 = 0; i2 < 4; i2++) {
                int v = v0 + ty * 4 + i2 + 64 * h;
                float4 w;
                w.x = facc[g * 4 + 0][h * 4 + i2] + bi[g * 4 + 0];
                w.y = facc[g * 4 + 1][h * 4 + i2] + bi[g * 4 + 1];
                w.z = facc[g * 4 + 2][h * 4 + i2] + bi[g * 4 + 2];
                w.w = facc[g * 4 + 3][h * 4 + i2] + bi[g * 4 + 3];
                *(float4*)(dst + (((size_t)v * 12 + he) * 64 + t) * 64 + cb) = w;
            }
    }
}

// ---------------------------------------------------------------------------
// 4) Attention: LN+int8 QK^T (dp4a), register softmax + int8 P, int8 PV.
// ---------------------------------------------------------------------------
__global__ void __launch_bounds__(256) attn_kernel(
        const float* __restrict__ qn_w, const float* __restrict__ qn_b,
        const float* __restrict__ kn_w, const float* __restrict__ kn_b) {
    __shared__ int   sqi[64 * 16];       // q int8 packed [row][word]
    __shared__ int   ski[64 * 17];       // k int8 packed, pitch 17
    __shared__ float sqs[64], sks[64];   // q/k per-row dequant scales
    __shared__ float sv[64 * 64];        // V fp32 [s][c]
    __shared__ int   svt[64 * 17];       // V^T int8 packed [c][word], pitch 17
    __shared__ float svs[64];            // per-column V scale
    __shared__ float sred[256];
    __shared__ int   spq[64 * 17];       // P int8 packed [row][word], pitch 17
    __shared__ float sps[64];            // per-row P scale
    const int tid = threadIdx.x;
    const int blk = blockIdx.x;
    const int he = blk % 12;
    const int v  = blk / 12;
    const float* qb = g_q + (size_t)blk * 4096;
    const float* kb = g_k + (size_t)blk * 4096;
    const float* vb = g_v + (size_t)blk * 4096;
    const int c0 = (tid & 15) * 4;
    const int wi = tid & 15;

    // kick off V loads
    #pragma unroll
    for (int it = 0; it < 4; it++) {
        int i = tid * 4 + it * 1024;
        cp16(&sv[i], vb + i);
    }
    asm volatile("cp.async.commit_group;" ::: "memory");

    const float4 qw4 = *(const float4*)(qn_w + c0);
    const float4 qb4 = *(const float4*)(qn_b + c0);
    const float4 kw4 = *(const float4*)(kn_w + c0);
    const float4 kb4 = *(const float4*)(kn_b + c0);

    #pragma unroll
    for (int it = 0; it < 4; it++) {
        int i = tid * 4 + it * 1024;
        int r = i >> 6;
        float4 qv = *(const float4*)(qb + i);
        {
            float s  = qv.x + qv.y + qv.z + qv.w;
            float s2 = qv.x * qv.x + qv.y * qv.y + qv.z * qv.z + qv.w * qv.w;
            s  += __shfl_xor_sync(0xffffffffu, s, 1);
            s2 += __shfl_xor_sync(0xffffffffu, s2, 1);
            s  += __shfl_xor_sync(0xffffffffu, s, 2);
            s2 += __shfl_xor_sync(0xffffffffu, s2, 2);
            s  += __shfl_xor_sync(0xffffffffu, s, 4);
            s2 += __shfl_xor_sync(0xffffffffu, s2, 4);
            s  += __shfl_xor_sync(0xffffffffu, s, 8);
            s2 += __shfl_xor_sync(0xffffffffu, s2, 8);
            float mu  = s * (1.f / 64.f);
            float var = s2 * (1.f / 64.f) - mu * mu;
            float inv = rsqrtf(var + 1e-5f);
            qv.x = (qv.x - mu) * inv * qw4.x + qb4.x;
            qv.y = (qv.y - mu) * inv * qw4.y + qb4.y;
            qv.z = (qv.z - mu) * inv * qw4.z + qb4.z;
            qv.w = (qv.w - mu) * inv * qw4.w + qb4.w;
            float m = fmaxf(fmaxf(fabsf(qv.x), fabsf(qv.y)),
                            fmaxf(fabsf(qv.z), fabsf(qv.w)));
            m = fmaxf(m, __shfl_xor_sync(0xffffffffu, m, 1));
            m = fmaxf(m, __shfl_xor_sync(0xffffffffu, m, 2));
            m = fmaxf(m, __shfl_xor_sync(0xffffffffu, m, 4));
            m = fmaxf(m, __shfl_xor_sync(0xffffffffu, m, 8));
            float invs = (m < 1e-30f) ? 0.f : 127.f / m;
            int word = q8(qv.x * invs)
                     | (q8(qv.y * invs) << 8)
                     | (q8(qv.z * invs) << 16)
                     | (q8(qv.w * invs) << 24);
            sqi[r * 16 + wi] = word;
            if (wi == 0) sqs[r] = (m < 1e-30f) ? 0.f : m * (1.f / 127.f);
        }
        float4 kv = *(const float4*)(kb + i);
        {
            float s  = kv.x + kv.y + kv.z + kv.w;
            float s2 = kv.x * kv.x + kv.y * kv.y + kv.z * kv.z + kv.w * kv.w;
            s  += __shfl_xor_sync(0xffffffffu, s, 1);
            s2 += __shfl_xor_sync(0xffffffffu, s2, 1);
            s  += __shfl_xor_sync(0xffffffffu, s, 2);
            s2 += __shfl_xor_sync(0xffffffffu, s2, 2);
            s  += __shfl_xor_sync(0xffffffffu, s, 4);
            s2 += __shfl_xor_sync(0xffffffffu, s2, 4);
            s  += __shfl_xor_sync(0xffffffffu, s, 8);
            s2 += __shfl_xor_sync(0xffffffffu, s2, 8);
            float mu  = s * (1.f / 64.f);
            float var = s2 * (1.f / 64.f) - mu * mu;
            float inv = rsqrtf(var + 1e-5f);
            kv.x = (kv.x - mu) * inv * kw4.x + kb4.x;
            kv.y = (kv.y - mu) * inv * kw4.y + kb4.y;
            kv.z = (kv.z - mu) * inv * kw4.z + kb4.z;
            kv.w = (kv.w - mu) * inv * kw4.w + kb4.w;
            float m = fmaxf(fmaxf(fabsf(kv.x), fabsf(kv.y)),
                            fmaxf(fabsf(kv.z), fabsf(kv.w)));
            m = fmaxf(m, __shfl_xor_sync(0xffffffffu, m, 1));
            m = fmaxf(m, __shfl_xor_sync(0xffffffffu, m, 2));
            m = fmaxf(m, __shfl_xor_sync(0xffffffffu, m, 4));
            m = fmaxf(m, __shfl_xor_sync(0xffffffffu, m, 8));
            float invs = (m < 1e-30f) ? 0.f : 127.f / m;
            int word = q8(kv.x * invs)
                     | (q8(kv.y * invs) << 8)
                     | (q8(kv.z * invs) << 16)
                     | (q8(kv.w * invs) << 24);
            ski[r * 17 + wi] = word;
            if (wi == 0) sks[r] = (m < 1e-30f) ? 0.f : m * (1.f / 127.f);
        }
    }
    __syncthreads();

    const int tx = tid & 15, ty = tid >> 4;
    const int t0 = ty * 4, s0 = tx * 4;

    // QK^T via dp4a -> registers
    int iacc[4][4];
    #pragma unroll
    for (int i = 0; i < 4; i++)
        #pragma unroll
        for (int j = 0; j < 4; j++) iacc[i][j] = 0;

    #pragma unroll
    for (int w = 0; w < 16; w++) {
        int a_[4], b_[4];
        #pragma unroll
        for (int i = 0; i < 4; i++) a_[i] = sqi[(t0 + i) * 16 + w];
        #pragma unroll
        for (int j = 0; j < 4; j++) b_[j] = ski[(s0 + j) * 17 + w];
        #pragma unroll
        for (int i = 0; i < 4; i++)
            #pragma unroll
            for (int j = 0; j < 4; j++)
                iacc[i][j] = __dp4a(a_[i], b_[j], iacc[i][j]);
    }

    float qsc[4], ksc[4];
    #pragma unroll
    for (int i = 0; i < 4; i++) qsc[i] = sqs[t0 + i] * 0.125f;
    #pragma unroll
    for (int j = 0; j < 4; j++) ksc[j] = sks[s0 + j];

    // scores in registers: s[i][j] = iacc*qsc*ksc + bias
    float sc_[4][4];
    const float* bb = g_bias + he * 4096;
    #pragma unroll
    for (int i = 0; i < 4; i++) {
        float4 bi = *(const float4*)(bb + (t0 + i) * 64 + s0);
        sc_[i][0] = fmaf((float)iacc[i][0], qsc[i] * ksc[0], bi.x);
        sc_[i][1] = fmaf((float)iacc[i][1], qsc[i] * ksc[1], bi.y);
        sc_[i][2] = fmaf((float)iacc[i][2], qsc[i] * ksc[2], bi.z);
        sc_[i][3] = fmaf((float)iacc[i][3], qsc[i] * ksc[3], bi.w);
    }

    // V quantize + transpose (overlaps register softmax data flow)
    asm volatile("cp.async.wait_group 0;" ::: "memory");
    __syncthreads();
    {
        const int cc = tid & 63;
        const int quar = tid >> 6;
        float m = 0.f;
        #pragma unroll
        for (int s = 0; s < 16; s++)
            m = fmaxf(m, fabsf(sv[(quar * 16 + s) * 64 + cc]));
        sred[tid] = m;
    }
    __syncthreads();
    if (tid < 64) {
        float m = fmaxf(fmaxf(sred[tid], sred[tid + 64]),
                        fmaxf(sred[tid + 128], sred[tid + 192]));
        svs[tid] = (m < 1e-30f) ? 0.f : m * (1.f / 127.f);
        sred[tid] = (m < 1e-30f) ? 0.f : 127.f / m;
    }
    __syncthreads();
    {
        const int cc = tid & 63;
        const int wg = tid >> 6;
        const float invv = sred[cc];
        #pragma unroll
        for (int w2 = 0; w2 < 4; w2++) {
            int w = wg * 4 + w2;
            int word = q8(sv[(4 * w + 0) * 64 + cc] * invv)
                     | (q8(sv[(4 * w + 1) * 64 + cc] * invv) << 8)
                     | (q8(sv[(4 * w + 2) * 64 + cc] * invv) << 16)
                     | (q8(sv[(4 * w + 3) * 64 + cc] * invv) << 24);
            svt[cc * 17 + w] = word;
        }
    }

    // register softmax over rows t0..t0+3 (16 tx lanes per row)
    #pragma unroll
    for (int i = 0; i < 4; i++) {
        float mx = fmaxf(fmaxf(sc_[i][0], sc_[i][1]), fmaxf(sc_[i][2], sc_[i][3]));
        mx = fmaxf(mx, __shfl_xor_sync(0xffffffffu, mx, 1));
        mx = fmaxf(mx, __shfl_xor_sync(0xffffffffu, mx, 2));
        mx = fmaxf(mx, __shfl_xor_sync(0xffffffffu, mx, 4));
        mx = fmaxf(mx, __shfl_xor_sync(0xffffffffu, mx, 8));
        float e0 = expf(sc_[i][0] - mx);
        float e1 = expf(sc_[i][1] - mx);
        float e2 = expf(sc_[i][2] - mx);
        float e3 = expf(sc_[i][3] - mx);
        float sum = e0 + e1 + e2 + e3;
        sum += __shfl_xor_sync(0xffffffffu, sum, 1);
        sum += __shfl_xor_sync(0xffffffffu, sum, 2);
        sum += __shfl_xor_sync(0xffffffffu, sum, 4);
        sum += __shfl_xor_sync(0xffffffffu, sum, 8);
        float rs = 1.f / sum;
        // p = e*rs, max(p)=rs -> quantized p = round(e*127), scale = rs/127
        int word = q8(e0 * 127.f)
                 | (q8(e1 * 127.f) << 8)
                 | (q8(e2 * 127.f) << 16)
                 | (q8(e3 * 127.f) << 24);
        spq[(t0 + i) * 17 + tx] = word;
        if (tx == 0) sps[t0 + i] = rs * (1.f / 127.f);
    }
    __syncthreads();

    // PV via dp4a: O[i][c] = ps[i]*vs[c]* sum_w dp4a(P[i][w], VT[c][w])
    int iacc2[4][4];
    #pragma unroll
    for (int i = 0; i < 4; i++)
        #pragma unroll
        for (int j = 0; j < 4; j++) iacc2[i][j] = 0;

    #pragma unroll
    for (int w = 0; w < 16; w++) {
        int p_[4], v_[4];
        #pragma unroll
        for (int i = 0; i < 4; i++) p_[i] = spq[(t0 + i) * 17 + w];
        #pragma unroll
        for (int j = 0; j < 4; j++) v_[j] = svt[(s0 + j) * 17 + w];
        #pragma unroll
        for (int i = 0; i < 4; i++)
            #pragma unroll
            for (int j = 0; j < 4; j++)
                iacc2[i][j] = __dp4a(p_[i], v_[j], iacc2[i][j]);
    }

    float psc[4], vsc[4];
    #pragma unroll
    for (int i = 0; i < 4; i++) psc[i] = sps[t0 + i];
    #pragma unroll
    for (int j = 0; j < 4; j++) vsc[j] = svs[s0 + j];

    float oacc[4][4];
    #pragma unroll
    for (int i = 0; i < 4; i++)
        #pragma unroll
        for (int j = 0; j < 4; j++)
            oacc[i][j] = (float)iacc2[i][j] * (psc[i] * vsc[j]);

    // quantize per (n, head) row for GEMM2
    #pragma unroll
    for (int i = 0; i < 4; i++) {
        float m = fmaxf(fmaxf(fabsf(oacc[i][0]), fabsf(oacc[i][1])),
                        fmaxf(fabsf(oacc[i][2]), fabsf(oacc[i][3])));
        m = fmaxf(m, __shfl_xor_sync(0xffffffffu, m, 1));
        m = fmaxf(m, __shfl_xor_sync(0xffffffffu, m, 2));
        m = fmaxf(m, __shfl_xor_sync(0xffffffffu, m, 4));
        m = fmaxf(m, __shfl_xor_sync(0xffffffffu, m, 8));
        float invs = (m < 1e-30f) ? 0.f : 127.f / m;
        float scl  = (m < 1e-30f) ? 0.f : m * (1.f / 127.f);
        int w = q8(oacc[i][0] * invs)
              | (q8(oacc[i][1] * invs) << 8)
              | (q8(oacc[i][2] * invs) << 16)
              | (q8(oacc[i][3] * invs) << 24);
        int n = (t0 + i) * 512 + v;
        g_oq[(size_t)n * 192 + he * 16 + tx] = w;
        if (tx == 0) g_sa2[(size_t)n * 12 + he] = scl;
    }
}

// ---------------------------------------------------------------------------
// 5) GEMM2 int8 dp4a: out = x + gamma*(o @ w_out^T + b_out)
// ---------------------------------------------------------------------------
__global__ void __launch_bounds__(256, 2) gemm_out_kernel(
        const float* __restrict__ x,
        const float* __restrict__ b_out,
        const float* __restrict__ gamma,
        float* __restrict__ out) {
    __shared__ int As[2][16 * 128];
    __shared__ int Bs[2][16 * 128];
    __shared__ float ssa[12 * 128];
    __shared__ float ssbs[12 * 128];
    const int tid = threadIdx.x;
    const int tx = tid & 15, ty = tid >> 4;
    const int n0 = blockIdx.y * 128;
    const int o0 = blockIdx.x * 128;
    const int t  = n0 >> 9;
    const int v0 = n0 & 511;

    for (int i = tid; i < 1536; i += 256) {
        ssa[i]  = g_sa2[(size_t)(n0 + (i & 127)) * 12 + (i >> 7)];
        ssbs[i] = g_sb2[(i >> 7) * 768 + o0 + (i & 127)];
    }

    const int nl = tid & 127;
    const int half = tid >> 7;
    const int kwl = tid >> 4;
    const int ocl = (tid & 15) * 8;

    float facc[8][8];
    #pragma unroll
    for (int p = 0; p < 8; p++)
        #pragma unroll
        for (int q = 0; q < 8; q++) facc[p][q] = 0.f;

    int4 pa0, pa1, pb0, pb1;
    {
        const int* asrc = g_oq + (size_t)(n0 + nl) * 192 + half * 8;
        pa0 = *(const int4*)(asrc);
        pa1 = *(const int4*)(asrc + 4);
        const int* bsrc = g_wq2 + (size_t)kwl * 768 + o0 + ocl;
        pb0 = *(const int4*)(bsrc);
        pb1 = *(const int4*)(bsrc + 4);
    }
    {
        int base = half * 8;
        As[0][(base + 0) * 128 + nl] = pa0.x;
        As[0][(base + 1) * 128 + nl] = pa0.y;
        As[0][(base + 2) * 128 + nl] = pa0.z;
        As[0][(base + 3) * 128 + nl] = pa0.w;
        As[0][(base + 4) * 128 + nl] = pa1.x;
        As[0][(base + 5) * 128 + nl] = pa1.y;
        As[0][(base + 6) * 128 + nl] = pa1.z;
        As[0][(base + 7) * 128 + nl] = pa1.w;
        *(int4*)&Bs[0][kwl * 128 + ocl]     = pb0;
        *(int4*)&Bs[0][kwl * 128 + ocl + 4] = pb1;
    }
    __syncthreads();

    for (int ch = 0; ch < 12; ch++) {
        const int st = ch & 1;
        if (ch < 11) {
            const int kw0 = (ch + 1) * 16;
            const int* asrc = g_oq + (size_t)(n0 + nl) * 192 + kw0 + half * 8;
            pa0 = *(const int4*)(asrc);
            pa1 = *(const int4*)(asrc + 4);
            const int* bsrc = g_wq2 + (size_t)(kw0 + kwl) * 768 + o0 + ocl;
            pb0 = *(const int4*)(bsrc);
            pb1 = *(const int4*)(bsrc + 4);
        }

        float sbv[8];
        #pragma unroll
        for (int g = 0; g < 2; g++)
            #pragma unroll
            for (int j = 0; j < 4; j++)
                sbv[g * 4 + j] = ssbs[ch * 128 + tx * 4 + j + 64 * g];

        #pragma unroll
        for (int h = 0; h < 2; h++) {
            int ia[8][4];
            #pragma unroll
            for (int p = 0; p < 8; p++)
                #pragma unroll
                for (int q = 0; q < 4; q++) ia[p][q] = 0;
            #pragma unroll
            for (int kw = 0; kw < 16; kw++) {
                int4 av = *(const int4*)&As[st][kw * 128 + ty * 4 + h * 64];
                int4 b0 = *(const int4*)&Bs[st][kw * 128 + tx * 4];
                int4 b1 = *(const int4*)&Bs[st][kw * 128 + tx * 4 + 64];
                int avv[4] = {av.x, av.y, av.z, av.w};
                int bov[8] = {b0.x, b0.y, b0.z, b0.w, b1.x, b1.y, b1.z, b1.w};
                #pragma unroll
                for (int p = 0; p < 8; p++)
                    #pragma unroll
                    for (int q = 0; q < 4; q++)
                        ia[p][q] = __dp4a(avv[q], bov[p], ia[p][q]);
            }
            float sav[4];
            #pragma unroll
            for (int q = 0; q < 4; q++)
                sav[q] = ssa[ch * 128 + ty * 4 + q + 64 * h];
            #pragma unroll
            for (int p = 0; p < 8; p++)
                #pragma unroll
                for (int q = 0; q < 4; q++)
                    facc[p][h * 4 + q] = fmaf((float)ia[p][q], sbv[p] * sav[q],
                                              facc[p][h * 4 + q]);
        }

        if (ch < 11) {
            const int ns = st ^ 1;
            __syncthreads();
            int base = half * 8;
            As[ns][(base + 0) * 128 + nl] = pa0.x;
            As[ns][(base + 1) * 128 + nl] = pa0.y;
            As[ns][(base + 2) * 128 + nl] = pa0.z;
            As[ns][(base + 3) * 128 + nl] = pa0.w;
            As[ns][(base + 4) * 128 + nl] = pa1.x;
            As[ns][(base + 5) * 128 + nl] = pa1.y;
            As[ns][(base + 6) * 128 + nl] = pa1.z;
            As[ns][(base + 7) * 128 + nl] = pa1.w;
            *(int4*)&Bs[ns][kwl * 128 + ocl]     = pb0;
            *(int4*)&Bs[ns][kwl * 128 + ocl + 4] = pb1;
            __syncthreads();
        }
    }

    #pragma unroll
    for (int p = 0; p < 8; p++) {
        const int oc = o0 + tx * 4 + (p & 3) + 64 * (p >> 2);
        const float bo = b_out[oc];
        const float gm = gamma[oc];
        #pragma unroll
        for (int h = 0; h < 2; h++) {
            size_t base = (size_t)t * 393216 + (size_t)oc * 512 + v0 + ty * 4 + 64 * h;
            float4 xv = *(const float4*)(x + base);
            float4 w;
            w.x = xv.x + gm * (facc[p][h * 4 + 0] + bo);
            w.y = xv.y + gm * (facc[p][h * 4 + 1] + bo);
            w.z = xv.z + gm * (facc[p][h * 4 + 2] + bo);
            w.w = xv.w + gm * (facc[p][h * 4 + 3] + bo);
            *(float4*)(out + base) = w;
        }
    }
}

// ---------------------------------------------------------------------------
extern "C" void kernel_launch(void* const* d_in, const int* in_sizes, int n_in,
                              void* d_out, int out_size) {
    const float* x      = (const float*)d_in[0];
    const float* norm1w = (const float*)d_in[1];
    const float* w_in   = (const float*)d_in[2];
    const float* b_in   = (const float*)d_in[3];
    const float* qn_w   = (const float*)d_in[4];
    const float* qn_b   = (const float*)d_in[5];
    const float* kn_w   = (const float*)d_in[6];
    const float* kn_b   = (const float*)d_in[7];
    const float* rel    = (const float*)d_in[8];
    const float* w_out  = (const float*)d_in[9];
    const float* b_out  = (const float*)d_in[10];
    const float* gamma  = (const float*)d_in[11];
    float* out = (float*)d_out;

    gn_stats_quant_kernel<<<768, 256>>>(x, norm1w);            // 0
    quant_wb_kernel<<<448, 256>>>(w_in, w_out, rel);           // 1
    gemm_qkv_kernel<<<dim3(18, 256), 256>>>(b_in);             // 2
    attn_kernel<<<6144, 256>>>(qn_w, qn_b, kn_w, kn_b);        // 3 (profiled)
    gemm_out_kernel<<<dim3(6, 256), 256>>>(x, b_out, gamma, out);  // 4
}

// round 15
// speedup vs baseline: 1.6531x; 1.1695x over previous
#include <cuda_runtime.h>
#include <stdint.h>
#include <math.h>

// Shapes (fixed): T=64, B=1, C=768, V=H*W*D=512, heads=12, hd=64, M=T*V=32768

__device__ float g_scale[64 * 768];
__device__ float g_shift[64 * 768];
__device__ float g_bnd[64 * 12];         // per-(t,group) |xn| bound
__device__ float g_qas[64];              // per-t dequant scale (bound/127)
__device__ float g_invqat[64];           // per-t 127/bound
__device__ float g_sbo[2304];            // w_in per-row scale
__device__ int   g_xq[64 * 192 * 512];   // x int8 packed: [t][kw][v]
__device__ int   g_wq[192 * 2304];       // w_in int8 packed: [kw][o]
__device__ float g_bias[12 * 64 * 64];
__device__ float g_q[512 * 12 * 64 * 64];
__device__ float g_k[512 * 12 * 64 * 64];
__device__ float g_v[512 * 12 * 64 * 64];
__device__ int   g_oq[32768 * 192];      // attn out int8 packed: [n][kw]
__device__ float g_sa2[32768 * 12];      // attn out scale per (n, head)
__device__ int   g_wq2[192 * 768];       // w_out int8 packed: [kw][oc]
__device__ float g_sb2[12 * 768];        // w_out scale per (chunk, oc)

__device__ __forceinline__ void cp16(void* smem, const void* g) {
    unsigned int s = (unsigned int)__cvta_generic_to_shared(smem);
    asm volatile("cp.async.cg.shared.global [%0], [%1], 16;" :: "r"(s), "l"(g));
}
__device__ __forceinline__ int q8(float f) {
    int q = __float2int_rn(f);
    q = q > 127 ? 127 : q;
    q = q < -127 ? -127 : q;
    return q & 0xFF;
}

// ---------------------------------------------------------------------------
// 1) GroupNorm stats: scale/shift per (t,c), |xn| bound per (t,g)
// ---------------------------------------------------------------------------
__global__ void gn_stats_kernel(const float* __restrict__ x,
                                const float* __restrict__ w) {
    const int t = blockIdx.x / 12;
    const int g = blockIdx.x % 12;
    const int tid = threadIdx.x;
    const int cl = tid >> 2;
    const int qq = tid & 3;
    const float* base = x + (size_t)t * 393216 + (size_t)(g * 64 + cl) * 512 + qq * 128;

    float s = 0.f, s2 = 0.f, mx = 0.f;
    #pragma unroll 8
    for (int i = 0; i < 32; i++) {
        float4 a = ((const float4*)base)[i];
        s  += a.x + a.y + a.z + a.w;
        s2 += a.x * a.x + a.y * a.y + a.z * a.z + a.w * a.w;
        mx = fmaxf(mx, fmaxf(fmaxf(fabsf(a.x), fabsf(a.y)), fmaxf(fabsf(a.z), fabsf(a.w))));
    }
    __shared__ float red[256], red2[256], rmax[256];
    red[tid] = s; red2[tid] = s2; rmax[tid] = mx;
    __syncthreads();
    for (int o = 128; o > 0; o >>= 1) {
        if (tid < o) {
            red[tid]  += red[tid + o];
            red2[tid] += red2[tid + o];
        }
        __syncthreads();
    }
    __shared__ float smu, sinv;
    if (tid == 0) {
        float mu  = red[0] * (1.f / 32768.f);
        float var = red2[0] * (1.f / 32768.f) - mu * mu;
        smu  = mu;
        sinv = rsqrtf(var + 1e-5f);
    }
    __syncthreads();
    const float mu = smu, inv = sinv;
    if (tid < 64) {
        float cm = fmaxf(fmaxf(rmax[tid * 4], rmax[tid * 4 + 1]),
                         fmaxf(rmax[tid * 4 + 2], rmax[tid * 4 + 3]));
        int c = g * 64 + tid;
        float sc = inv * w[c];
        g_scale[t * 768 + c] = sc;
        g_shift[t * 768 + c] = -mu * sc;
        red[tid] = fabsf(sc) * (cm + fabsf(mu));
    }
    __syncthreads();
    for (int o = 32; o > 0; o >>= 1) {
        if (tid < o && tid + o < 64) red[tid] = fmaxf(red[tid], red[tid + o]);
        __syncthreads();
    }
    if (tid == 0) g_bnd[blockIdx.x] = red[0];
}

// ---------------------------------------------------------------------------
// 2) Weight quantization + bias table + per-t bound reduce.
//    blocks [0,288): w_in (per-row scale); [288,384): w_out (per-chunk);
//    [384,448): bias table; 448: per-t bound reduce.
// ---------------------------------------------------------------------------
__global__ void __launch_bounds__(256) quant_wb_kernel(
        const float* __restrict__ w_in,
        const float* __restrict__ w_out,
        const float* __restrict__ emb) {
    const int b = blockIdx.x;
    const int tid = threadIdx.x;
    if (b < 288) {
        // w_in: warp per o-row, single scale per row
        const int o = b * 8 + (tid >> 5);
        const int lane = tid & 31;
        float4 wv[6];
        float m = 0.f;
        #pragma unroll
        for (int r = 0; r < 6; r++) {
            wv[r] = *(const float4*)(w_in + (size_t)o * 768 + r * 128 + lane * 4);
            m = fmaxf(m, fmaxf(fmaxf(fabsf(wv[r].x), fabsf(wv[r].y)),
                               fmaxf(fabsf(wv[r].z), fabsf(wv[r].w))));
        }
        #pragma unroll
        for (int s = 16; s; s >>= 1) m = fmaxf(m, __shfl_xor_sync(0xffffffffu, m, s));
        float invw = (m < 1e-30f) ? 0.f : 127.f / m;
        #pragma unroll
        for (int r = 0; r < 6; r++) {
            int word = (q8(wv[r].x * invw))
                     | (q8(wv[r].y * invw) << 8)
                     | (q8(wv[r].z * invw) << 16)
                     | (q8(wv[r].w * invw) << 24);
            g_wq[(size_t)(r * 32 + lane) * 2304 + o] = word;
        }
        if (lane == 0) g_sbo[o] = (m < 1e-30f) ? 0.f : m * (1.f / 127.f);
    } else if (b < 384) {
        const int o = (b - 288) * 8 + (tid >> 5);
        const int lane = tid & 31;
        #pragma unroll
        for (int ch = 0; ch < 12; ch++) {
            float4 wv = *(const float4*)(w_out + (size_t)o * 768 + ch * 64 + (lane & 15) * 4);
            float m = fmaxf(fmaxf(fabsf(wv.x), fabsf(wv.y)), fmaxf(fabsf(wv.z), fabsf(wv.w)));
            #pragma unroll
            for (int s = 16; s; s >>= 1) m = fmaxf(m, __shfl_xor_sync(0xffffffffu, m, s));
            float sc, invw;
            if (m < 1e-30f) { sc = 0.f; invw = 0.f; }
            else            { sc = m * (1.f / 127.f); invw = 127.f / m; }
            if (lane < 16) {
                int word = (q8(wv.x * invw))
                         | (q8(wv.y * invw) << 8)
                         | (q8(wv.z * invw) << 16)
                         | (q8(wv.w * invw) << 24);
                g_wq2[(size_t)(ch * 16 + lane) * 768 + o] = word;
            }
            if (lane == 0) g_sb2[ch * 768 + o] = sc;
        }
    } else if (b < 448) {
        if (tid >= 64) return;
        const int t = b - 384;
        const int s = tid;
        int rel = t - s;
        int ret = rel < 0 ? 16 : 0;
        int n = rel < 0 ? -rel : rel;
        int bk;
        if (n < 8) {
            bk = n;
        } else {
            float f = logf((float)n / 8.0f);
            f = f / 2.772588722239781f;
            f = f * 8.0f;
            bk = 8 + (int)f;
            if (bk > 15) bk = 15;
        }
        int bucket = ret + bk;
        #pragma unroll
        for (int he = 0; he < 12; he++)
            g_bias[he * 4096 + t * 64 + s] = emb[bucket * 12 + he];
    } else {
        if (tid < 64) {
            float m = 0.f;
            #pragma unroll
            for (int g = 0; g < 12; g++) m = fmaxf(m, g_bnd[tid * 12 + g]);
            g_qas[tid]    = (m < 1e-30f) ? 0.f : m * (1.f / 127.f);
            g_invqat[tid] = (m < 1e-30f) ? 0.f : 127.f / m;
        }
    }
}

// ---------------------------------------------------------------------------
// 2b) quantize + k-pack xn -> g_xq[t][kw][v], per-t single scale
// ---------------------------------------------------------------------------
__global__ void __launch_bounds__(256) quant_x_kernel(const float* __restrict__ x) {
    const int t = blockIdx.x / 12;
    const int g = blockIdx.x % 12;
    const int tid = threadIdx.x;
    __shared__ float ssc[64], ssh[64];
    if (tid < 64) {
        float qinv = g_invqat[t];
        ssc[tid] = g_scale[t * 768 + g * 64 + tid] * qinv;
        ssh[tid] = g_shift[t * 768 + g * 64 + tid] * qinv;
    }
    __syncthreads();
    const float* xg = x + (size_t)t * 393216 + (size_t)g * 64 * 512;
    for (int i = tid; i < 2048; i += 256) {
        int kwl = i >> 7;
        int vb  = (i & 127) * 4;
        int c0  = kwl * 4;
        int wd[4] = {0, 0, 0, 0};
        #pragma unroll
        for (int r = 0; r < 4; r++) {
            int c = c0 + r;
            float scm = ssc[c];
            float shm = ssh[c];
            float4 f = *(const float4*)(xg + (size_t)c * 512 + vb);
            wd[0] |= q8(fmaf(f.x, scm, shm)) << (8 * r);
            wd[1] |= q8(fmaf(f.y, scm, shm)) << (8 * r);
            wd[2] |= q8(fmaf(f.z, scm, shm)) << (8 * r);
            wd[3] |= q8(fmaf(f.w, scm, shm)) << (8 * r);
        }
        *(int4*)(g_xq + ((size_t)t * 192 + g * 16 + kwl) * 512 + vb) =
            make_int4(wd[0], wd[1], wd[2], wd[3]);
    }
}

// ---------------------------------------------------------------------------
// 3) GEMM1 int8 dp4a, int32 accumulation over full K (single-scale dequant).
// ---------------------------------------------------------------------------
__global__ void __launch_bounds__(256, 2) gemm_qkv_kernel(
        const float* __restrict__ b_in) {
    __shared__ int As[2][16 * 128];
    __shared__ int Bs[2][16 * 128];
    const int tid = threadIdx.x;
    const int tx = tid & 15, ty = tid >> 4;
    const int n0 = blockIdx.y * 128;
    const int o0 = blockIdx.x * 128;
    const int t  = n0 >> 9;
    const int v0 = n0 & 511;
    const int lrow = tid >> 5;
    const int lcol = (tid & 31) * 4;

    int iacc[8][8];
    #pragma unroll
    for (int p = 0; p < 8; p++)
        #pragma unroll
        for (int q = 0; q < 8; q++) iacc[p][q] = 0;

    #pragma unroll
    for (int r = 0; r < 2; r++) {
        int row = lrow + r * 8;
        cp16(&As[0][row * 128 + lcol], g_xq + ((size_t)t * 192 + row) * 512 + v0 + lcol);
        cp16(&Bs[0][row * 128 + lcol], g_wq + (size_t)row * 2304 + o0 + lcol);
    }
    asm volatile("cp.async.commit_group;" ::: "memory");

    for (int ch = 0; ch < 12; ch++) {
        if (ch < 11) {
            const int ns = (ch + 1) & 1;
            const int kw0 = (ch + 1) * 16;
            #pragma unroll
            for (int r = 0; r < 2; r++) {
                int row = lrow + r * 8;
                cp16(&As[ns][row * 128 + lcol],
                     g_xq + ((size_t)t * 192 + kw0 + row) * 512 + v0 + lcol);
                cp16(&Bs[ns][row * 128 + lcol],
                     g_wq + (size_t)(kw0 + row) * 2304 + o0 + lcol);
            }
            asm volatile("cp.async.commit_group;" ::: "memory");
            asm volatile("cp.async.wait_group 1;" ::: "memory");
        } else {
            asm volatile("cp.async.wait_group 0;" ::: "memory");
        }
        __syncthreads();
        const int st = ch & 1;

        #pragma unroll
        for (int kw = 0; kw < 16; kw++) {
            int4 a0 = *(const int4*)&As[st][kw * 128 + ty * 4];
            int4 a1 = *(const int4*)&As[st][kw * 128 + ty * 4 + 64];
            int4 b0 = *(const int4*)&Bs[st][kw * 128 + tx * 4];
            int4 b1 = *(const int4*)&Bs[st][kw * 128 + tx * 4 + 64];
            int avv[8] = {a0.x, a0.y, a0.z, a0.w, a1.x, a1.y, a1.z, a1.w};
            int bov[8] = {b0.x, b0.y, b0.z, b0.w, b1.x, b1.y, b1.z, b1.w};
            #pragma unroll
            for (int p = 0; p < 8; p++)
                #pragma unroll
                for (int q = 0; q < 8; q++)
                    iacc[p][q] = __dp4a(avv[q], bov[p], iacc[p][q]);
        }
        __syncthreads();
    }

    const float sa = g_qas[t];
    float sbv[8], bi[8];
    #pragma unroll
    for (int g = 0; g < 2; g++)
        #pragma unroll
        for (int j = 0; j < 4; j++) {
            int o = o0 + tx * 4 + j + 64 * g;
            sbv[g * 4 + j] = sa * g_sbo[o];
            bi[g * 4 + j]  = b_in[o];
        }

    #pragma unroll
    for (int g = 0; g < 2; g++) {
        const int ob = o0 + tx * 4 + 64 * g;
        const int he = ob / 192;
        const int jj = ob - he * 192;
        const int part = jj >> 6;
        const int cb = jj & 63;
        float* dst = part == 0 ? g_q : (part == 1 ? g_k : g_v);
        #pragma unroll
        for (int h = 0; h < 2; h++)
            #pragma unroll
            for (int i2 = 0; i2 < 4; i2++) {
                int v = v0 + ty * 4 + i2 + 64 * h;
                float4 w;
                w.x = fmaf((float)iacc[g * 4 + 0][h * 4 + i2], sbv[g * 4 + 0], bi[g * 4 + 0]);
                w.y = fmaf((float)iacc[g * 4 + 1][h * 4 + i2], sbv[g * 4 + 1], bi[g * 4 + 1]);
                w.z = fmaf((float)iacc[g * 4 + 2][h * 4 + i2], sbv[g * 4 + 2], bi[g * 4 + 2]);
                w.w = fmaf((float)iacc[g * 4 + 3][h * 4 + i2], sbv[g * 4 + 3], bi[g * 4 + 3]);
                *(float4*)(dst + (((size_t)v * 12 + he) * 64 + t) * 64 + cb) = w;
            }
    }
}

// ---------------------------------------------------------------------------
// 4) Attention: LN+int8 QK^T (dp4a), register softmax + int8 P, int8 PV.
// ---------------------------------------------------------------------------
__global__ void __launch_bounds__(256) attn_kernel(
        const float* __restrict__ qn_w, const float* __restrict__ qn_b,
        const float* __restrict__ kn_w, const float* __restrict__ kn_b) {
    __shared__ int   sqi[64 * 16];
    __shared__ int   ski[64 * 17];
    __shared__ float sqs[64], sks[64];
    __shared__ float sv[64 * 64];
    __shared__ int   svt[64 * 17];
    __shared__ float svs[64];
    __shared__ float sred[256];
    __shared__ int   spq[64 * 17];
    __shared__ float sps[64];
    const int tid = threadIdx.x;
    const int blk = blockIdx.x;
    const int he = blk % 12;
    const int v  = blk / 12;
    const float* qb = g_q + (size_t)blk * 4096;
    const float* kb = g_k + (size_t)blk * 4096;
    const float* vb = g_v + (size_t)blk * 4096;
    const int c0 = (tid & 15) * 4;
    const int wi = tid & 15;

    #pragma unroll
    for (int it = 0; it < 4; it++) {
        int i = tid * 4 + it * 1024;
        cp16(&sv[i], vb + i);
    }
    asm volatile("cp.async.commit_group;" ::: "memory");

    const float4 qw4 = *(const float4*)(qn_w + c0);
    const float4 qb4 = *(const float4*)(qn_b + c0);
    const float4 kw4 = *(const float4*)(kn_w + c0);
    const float4 kb4 = *(const float4*)(kn_b + c0);

    #pragma unroll
    for (int it = 0; it < 4; it++) {
        int i = tid * 4 + it * 1024;
        int r = i >> 6;
        float4 qv = *(const float4*)(qb + i);
        {
            float s  = qv.x + qv.y + qv.z + qv.w;
            float s2 = qv.x * qv.x + qv.y * qv.y + qv.z * qv.z + qv.w * qv.w;
            s  += __shfl_xor_sync(0xffffffffu, s, 1);
            s2 += __shfl_xor_sync(0xffffffffu, s2, 1);
            s  += __shfl_xor_sync(0xffffffffu, s, 2);
            s2 += __shfl_xor_sync(0xffffffffu, s2, 2);
            s  += __shfl_xor_sync(0xffffffffu, s, 4);
            s2 += __shfl_xor_sync(0xffffffffu, s2, 4);
            s  += __shfl_xor_sync(0xffffffffu, s, 8);
            s2 += __shfl_xor_sync(0xffffffffu, s2, 8);
            float mu  = s * (1.f / 64.f);
            float var = s2 * (1.f / 64.f) - mu * mu;
            float inv = rsqrtf(var + 1e-5f);
            qv.x = (qv.x - mu) * inv * qw4.x + qb4.x;
            qv.y = (qv.y - mu) * inv * qw4.y + qb4.y;
            qv.z = (qv.z - mu) * inv * qw4.z + qb4.z;
            qv.w = (qv.w - mu) * inv * qw4.w + qb4.w;
            float m = fmaxf(fmaxf(fabsf(qv.x), fabsf(qv.y)),
                            fmaxf(fabsf(qv.z), fabsf(qv.w)));
            m = fmaxf(m, __shfl_xor_sync(0xffffffffu, m, 1));
            m = fmaxf(m, __shfl_xor_sync(0xffffffffu, m, 2));
            m = fmaxf(m, __shfl_xor_sync(0xffffffffu, m, 4));
            m = fmaxf(m, __shfl_xor_sync(0xffffffffu, m, 8));
            float invs = (m < 1e-30f) ? 0.f : 127.f / m;
            int word = q8(qv.x * invs)
                     | (q8(qv.y * invs) << 8)
                     | (q8(qv.z * invs) << 16)
                     | (q8(qv.w * invs) << 24);
            sqi[r * 16 + wi] = word;
            if (wi == 0) sqs[r] = (m < 1e-30f) ? 0.f : m * (1.f / 127.f);
        }
        float4 kv = *(const float4*)(kb + i);
        {
            float s  = kv.x + kv.y + kv.z + kv.w;
            float s2 = kv.x * kv.x + kv.y * kv.y + kv.z * kv.z + kv.w * kv.w;
            s  += __shfl_xor_sync(0xffffffffu, s, 1);
            s2 += __shfl_xor_sync(0xffffffffu, s2, 1);
            s  += __shfl_xor_sync(0xffffffffu, s, 2);
            s2 += __shfl_xor_sync(0xffffffffu, s2, 2);
            s  += __shfl_xor_sync(0xffffffffu, s, 4);
            s2 += __shfl_xor_sync(0xffffffffu, s2, 4);
            s  += __shfl_xor_sync(0xffffffffu, s, 8);
            s2 += __shfl_xor_sync(0xffffffffu, s2, 8);
            float mu  = s * (1.f / 64.f);
            float var = s2 * (1.f / 64.f) - mu * mu;
            float inv = rsqrtf(var + 1e-5f);
            kv.x = (kv.x - mu) * inv * kw4.x + kb4.x;
            kv.y = (kv.y - mu) * inv * kw4.y + kb4.y;
            kv.z = (kv.z - mu) * inv * kw4.z + kb4.z;
            kv.w = (kv.w - mu) * inv * kw4.w + kb4.w;
            float m = fmaxf(fmaxf(fabsf(kv.x), fabsf(kv.y)),
                            fmaxf(fabsf(kv.z), fabsf(kv.w)));
            m = fmaxf(m, __shfl_xor_sync(0xffffffffu, m, 1));
            m = fmaxf(m, __shfl_xor_sync(0xffffffffu, m, 2));
            m = fmaxf(m, __shfl_xor_sync(0xffffffffu, m, 4));
            m = fmaxf(m, __shfl_xor_sync(0xffffffffu, m, 8));
            float invs = (m < 1e-30f) ? 0.f : 127.f / m;
            int word = q8(kv.x * invs)
                     | (q8(kv.y * invs) << 8)
                     | (q8(kv.z * invs) << 16)
                     | (q8(kv.w * invs) << 24);
            ski[r * 17 + wi] = word;
            if (wi == 0) sks[r] = (m < 1e-30f) ? 0.f : m * (1.f / 127.f);
        }
    }
    __syncthreads();

    const int tx = tid & 15, ty = tid >> 4;
    const int t0 = ty * 4, s0 = tx * 4;

    int iacc[4][4];
    #pragma unroll
    for (int i = 0; i < 4; i++)
        #pragma unroll
        for (int j = 0; j < 4; j++) iacc[i][j] = 0;

    #pragma unroll
    for (int w = 0; w < 16; w++) {
        int a_[4], b_[4];
        #pragma unroll
        for (int i = 0; i < 4; i++) a_[i] = sqi[(t0 + i) * 16 + w];
        #pragma unroll
        for (int j = 0; j < 4; j++) b_[j] = ski[(s0 + j) * 17 + w];
        #pragma unroll
        for (int i = 0; i < 4; i++)
            #pragma unroll
            for (int j = 0; j < 4; j++)
                iacc[i][j] = __dp4a(a_[i], b_[j], iacc[i][j]);
    }

    float qsc[4], ksc[4];
    #pragma unroll
    for (int i = 0; i < 4; i++) qsc[i] = sqs[t0 + i] * 0.125f;
    #pragma unroll
    for (int j = 0; j < 4; j++) ksc[j] = sks[s0 + j];

    float sc_[4][4];
    const float* bb = g_bias + he * 4096;
    #pragma unroll
    for (int i = 0; i < 4; i++) {
        float4 bi = *(const float4*)(bb + (t0 + i) * 64 + s0);
        sc_[i][0] = fmaf((float)iacc[i][0], qsc[i] * ksc[0], bi.x);
        sc_[i][1] = fmaf((float)iacc[i][1], qsc[i] * ksc[1], bi.y);
        sc_[i][2] = fmaf((float)iacc[i][2], qsc[i] * ksc[2], bi.z);
        sc_[i][3] = fmaf((float)iacc[i][3], qsc[i] * ksc[3], bi.w);
    }

    asm volatile("cp.async.wait_group 0;" ::: "memory");
    __syncthreads();
    {
        const int cc = tid & 63;
        const int quar = tid >> 6;
        float m = 0.f;
        #pragma unroll
        for (int s = 0; s < 16; s++)
            m = fmaxf(m, fabsf(sv[(quar * 16 + s) * 64 + cc]));
        sred[tid] = m;
    }
    __syncthreads();
    if (tid < 64) {
        float m = fmaxf(fmaxf(sred[tid], sred[tid + 64]),
                        fmaxf(sred[tid + 128], sred[tid + 192]));
        svs[tid] = (m < 1e-30f) ? 0.f : m * (1.f / 127.f);
        sred[tid] = (m < 1e-30f) ? 0.f : 127.f / m;
    }
    __syncthreads();
    {
        const int cc = tid & 63;
        const int wg = tid >> 6;
        const float invv = sred[cc];
        #pragma unroll
        for (int w2 = 0; w2 < 4; w2++) {
            int w = wg * 4 + w2;
            int word = q8(sv[(4 * w + 0) * 64 + cc] * invv)
                     | (q8(sv[(4 * w + 1) * 64 + cc] * invv) << 8)
                     | (q8(sv[(4 * w + 2) * 64 + cc] * invv) << 16)
                     | (q8(sv[(4 * w + 3) * 64 + cc] * invv) << 24);
            svt[cc * 17 + w] = word;
        }
    }

    #pragma unroll
    for (int i = 0; i < 4; i++) {
        float mx = fmaxf(fmaxf(sc_[i][0], sc_[i][1]), fmaxf(sc_[i][2], sc_[i][3]));
        mx = fmaxf(mx, __shfl_xor_sync(0xffffffffu, mx, 1));
        mx = fmaxf(mx, __shfl_xor_sync(0xffffffffu, mx, 2));
        mx = fmaxf(mx, __shfl_xor_sync(0xffffffffu, mx, 4));
        mx = fmaxf(mx, __shfl_xor_sync(0xffffffffu, mx, 8));
        float e0 = expf(sc_[i][0] - mx);
        float e1 = expf(sc_[i][1] - mx);
        float e2 = expf(sc_[i][2] - mx);
        float e3 = expf(sc_[i][3] - mx);
        float sum = e0 + e1 + e2 + e3;
        sum += __shfl_xor_sync(0xffffffffu, sum, 1);
        sum += __shfl_xor_sync(0xffffffffu, sum, 2);
        sum += __shfl_xor_sync(0xffffffffu, sum, 4);
        sum += __shfl_xor_sync(0xffffffffu, sum, 8);
        float rs = 1.f / sum;
        int word = q8(e0 * 127.f)
                 | (q8(e1 * 127.f) << 8)
                 | (q8(e2 * 127.f) << 16)
                 | (q8(e3 * 127.f) << 24);
        spq[(t0 + i) * 17 + tx] = word;
        if (tx == 0) sps[t0 + i] = rs * (1.f / 127.f);
    }
    __syncthreads();

    int iacc2[4][4];
    #pragma unroll
    for (int i = 0; i < 4; i++)
        #pragma unroll
        for (int j = 0; j < 4; j++) iacc2[i][j] = 0;

    #pragma unroll
    for (int w = 0; w < 16; w++) {
        int p_[4], v_[4];
        #pragma unroll
        for (int i = 0; i < 4; i++) p_[i] = spq[(t0 + i) * 17 + w];
        #pragma unroll
        for (int j = 0; j < 4; j++) v_[j] = svt[(s0 + j) * 17 + w];
        #pragma unroll
        for (int i = 0; i < 4; i++)
            #pragma unroll
            for (int j = 0; j < 4; j++)
                iacc2[i][j] = __dp4a(p_[i], v_[j], iacc2[i][j]);
    }

    float psc[4], vsc[4];
    #pragma unroll
    for (int i = 0; i < 4; i++) psc[i] = sps[t0 + i];
    #pragma unroll
    for (int j = 0; j < 4; j++) vsc[j] = svs[s0 + j];

    float oacc[4][4];
    #pragma unroll
    for (int i = 0; i < 4; i++)
        #pragma unroll
        for (int j = 0; j < 4; j++)
            oacc[i][j] = (float)iacc2[i][j] * (psc[i] * vsc[j]);

    #pragma unroll
    for (int i = 0; i < 4; i++) {
        float m = fmaxf(fmaxf(fabsf(oacc[i][0]), fabsf(oacc[i][1])),
                        fmaxf(fabsf(oacc[i][2]), fabsf(oacc[i][3])));
        m = fmaxf(m, __shfl_xor_sync(0xffffffffu, m, 1));
        m = fmaxf(m, __shfl_xor_sync(0xffffffffu, m, 2));
        m = fmaxf(m, __shfl_xor_sync(0xffffffffu, m, 4));
        m = fmaxf(m, __shfl_xor_sync(0xffffffffu, m, 8));
        float invs = (m < 1e-30f) ? 0.f : 127.f / m;
        float scl  = (m < 1e-30f) ? 0.f : m * (1.f / 127.f);
        int w = q8(oacc[i][0] * invs)
              | (q8(oacc[i][1] * invs) << 8)
              | (q8(oacc[i][2] * invs) << 16)
              | (q8(oacc[i][3] * invs) << 24);
        int n = (t0 + i) * 512 + v;
        g_oq[(size_t)n * 192 + he * 16 + tx] = w;
        if (tx == 0) g_sa2[(size_t)n * 12 + he] = scl;
    }
}

// ---------------------------------------------------------------------------
// 5) GEMM2 int8 dp4a: out = x + gamma*(o @ w_out^T + b_out)
// ---------------------------------------------------------------------------
__global__ void __launch_bounds__(256, 2) gemm_out_kernel(
        const float* __restrict__ x,
        const float* __restrict__ b_out,
        const float* __restrict__ gamma,
        float* __restrict__ out) {
    __shared__ int As[2][16 * 128];
    __shared__ int Bs[2][16 * 128];
    __shared__ float ssa[12 * 128];
    __shared__ float ssbs[12 * 128];
    const int tid = threadIdx.x;
    const int tx = tid & 15, ty = tid >> 4;
    const int n0 = blockIdx.y * 128;
    const int o0 = blockIdx.x * 128;
    const int t  = n0 >> 9;
    const int v0 = n0 & 511;

    for (int i = tid; i < 1536; i += 256) {
        ssa[i]  = g_sa2[(size_t)(n0 + (i & 127)) * 12 + (i >> 7)];
        ssbs[i] = g_sb2[(i >> 7) * 768 + o0 + (i & 127)];
    }

    const int nl = tid & 127;
    const int half = tid >> 7;
    const int kwl = tid >> 4;
    const int ocl = (tid & 15) * 8;

    float facc[8][8];
    #pragma unroll
    for (int p = 0; p < 8; p++)
        #pragma unroll
        for (int q = 0; q < 8; q++) facc[p][q] = 0.f;

    int4 pa0, pa1, pb0, pb1;
    {
        const int* asrc = g_oq + (size_t)(n0 + nl) * 192 + half * 8;
        pa0 = *(const int4*)(asrc);
        pa1 = *(const int4*)(asrc + 4);
        const int* bsrc = g_wq2 + (size_t)kwl * 768 + o0 + ocl;
        pb0 = *(const int4*)(bsrc);
        pb1 = *(const int4*)(bsrc + 4);
    }
    {
        int base = half * 8;
        As[0][(base + 0) * 128 + nl] = pa0.x;
        As[0][(base + 1) * 128 + nl] = pa0.y;
        As[0][(base + 2) * 128 + nl] = pa0.z;
        As[0][(base + 3) * 128 + nl] = pa0.w;
        As[0][(base + 4) * 128 + nl] = pa1.x;
        As[0][(base + 5) * 128 + nl] = pa1.y;
        As[0][(base + 6) * 128 + nl] = pa1.z;
        As[0][(base + 7) * 128 + nl] = pa1.w;
        *(int4*)&Bs[0][kwl * 128 + ocl]     = pb0;
        *(int4*)&Bs[0][kwl * 128 + ocl + 4] = pb1;
    }
    __syncthreads();

    for (int ch = 0; ch < 12; ch++) {
        const int st = ch & 1;
        if (ch < 11) {
            const int kw0 = (ch + 1) * 16;
            const int* asrc = g_oq + (size_t)(n0 + nl) * 192 + kw0 + half * 8;
            pa0 = *(const int4*)(asrc);
            pa1 = *(const int4*)(asrc + 4);
            const int* bsrc = g_wq2 + (size_t)(kw0 + kwl) * 768 + o0 + ocl;
            pb0 = *(const int4*)(bsrc);
            pb1 = *(const int4*)(bsrc + 4);
        }

        float sbv[8];
        #pragma unroll
        for (int g = 0; g < 2; g++)
            #pragma unroll
            for (int j = 0; j < 4; j++)
                sbv[g * 4 + j] = ssbs[ch * 128 + tx * 4 + j + 64 * g];

        #pragma unroll
        for (int h = 0; h < 2; h++) {
            int ia[8][4];
            #pragma unroll
            for (int p = 0; p < 8; p++)
                #pragma unroll
                for (int q = 0; q < 4; q++) ia[p][q] = 0;
            #pragma unroll
            for (int kw = 0; kw < 16; kw++) {
                int4 av = *(const int4*)&As[st][kw * 128 + ty * 4 + h * 64];
                int4 b0 = *(const int4*)&Bs[st][kw * 128 + tx * 4];
                int4 b1 = *(const int4*)&Bs[st][kw * 128 + tx * 4 + 64];
                int avv[4] = {av.x, av.y, av.z, av.w};
                int bov[8] = {b0.x, b0.y, b0.z, b0.w, b1.x, b1.y, b1.z, b1.w};
                #pragma unroll
                for (int p = 0; p < 8; p++)
                    #pragma unroll
                    for (int q = 0; q < 4; q++)
                        ia[p][q] = __dp4a(avv[q], bov[p], ia[p][q]);
            }
            float sav[4];
            #pragma unroll
            for (int q = 0; q < 4; q++)
                sav[q] = ssa[ch * 128 + ty * 4 + q + 64 * h];
            #pragma unroll
            for (int p = 0; p < 8; p++)
                #pragma unroll
                for (int q = 0; q < 4; q++)
                    facc[p][h * 4 + q] = fmaf((float)ia[p][q], sbv[p] * sav[q],
                                              facc[p][h * 4 + q]);
        }

        if (ch < 11) {
            const int ns = st ^ 1;
            __syncthreads();
            int base = half * 8;
            As[ns][(base + 0) * 128 + nl] = pa0.x;
            As[ns][(base + 1) * 128 + nl] = pa0.y;
            As[ns][(base + 2) * 128 + nl] = pa0.z;
            As[ns][(base + 3) * 128 + nl] = pa0.w;
            As[ns][(base + 4) * 128 + nl] = pa1.x;
            As[ns][(base + 5) * 128 + nl] = pa1.y;
            As[ns][(base + 6) * 128 + nl] = pa1.z;
            As[ns][(base + 7) * 128 + nl] = pa1.w;
            *(int4*)&Bs[ns][kwl * 128 + ocl]     = pb0;
            *(int4*)&Bs[ns][kwl * 128 + ocl + 4] = pb1;
            __syncthreads();
        }
    }

    #pragma unroll
    for (int p = 0; p < 8; p++) {
        const int oc = o0 + tx * 4 + (p & 3) + 64 * (p >> 2);
        const float bo = b_out[oc];
        const float gm = gamma[oc];
        #pragma unroll
        for (int h = 0; h < 2; h++) {
            size_t base = (size_t)t * 393216 + (size_t)oc * 512 + v0 + ty * 4 + 64 * h;
            float4 xv = *(const float4*)(x + base);
            float4 w;
            w.x = xv.x + gm * (facc[p][h * 4 + 0] + bo);
            w.y = xv.y + gm * (facc[p][h * 4 + 1] + bo);
            w.z = xv.z + gm * (facc[p][h * 4 + 2] + bo);
            w.w = xv.w + gm * (facc[p][h * 4 + 3] + bo);
            *(float4*)(out + base) = w;
        }
    }
}

// ---------------------------------------------------------------------------
extern "C" void kernel_launch(void* const* d_in, const int* in_sizes, int n_in,
                              void* d_out, int out_size) {
    const float* x      = (const float*)d_in[0];
    const float* norm1w = (const float*)d_in[1];
    const float* w_in   = (const float*)d_in[2];
    const float* b_in   = (const float*)d_in[3];
    const float* qn_w   = (const float*)d_in[4];
    const float* qn_b   = (const float*)d_in[5];
    const float* kn_w   = (const float*)d_in[6];
    const float* kn_b   = (const float*)d_in[7];
    const float* rel    = (const float*)d_in[8];
    const float* w_out  = (const float*)d_in[9];
    const float* b_out  = (const float*)d_in[10];
    const float* gamma  = (const float*)d_in[11];
    float* out = (float*)d_out;

    gn_stats_kernel<<<768, 256>>>(x, norm1w);                  // 0
    quant_wb_kernel<<<449, 256>>>(w_in, w_out, rel);           // 1
    quant_x_kernel<<<768, 256>>>(x);                           // 2
    gemm_qkv_kernel<<<dim3(18, 256), 256>>>(b_in);             // 3 (profiled)
    attn_kernel<<<6144, 256>>>(qn_w, qn_b, kn_w, kn_b);        // 4
    gemm_out_kernel<<<dim3(6, 256), 256>>>(x, b_out, gamma, out);  // 5
}